// round 2
// baseline (speedup 1.0000x reference)
#include <cuda_runtime.h>
#include <math.h>

#define N_NODES 4096
#define M_NODES 8192
#define DIM 128
#define NUM_ITERS 3

// Scratch (device globals; no allocations allowed)
__device__ float g_Xu[M_NODES * DIM];
__device__ float g_Y[M_NODES * DIM];
__device__ float g_dinv[M_NODES];

// ---------------------------------------------------------------------------
// Generic tiled GEMM with epilogue:
//   C[i,j] = epi( sum_k A[i,k]*B[k,j] )
//   epi(v) = maybe_relu( v*rs[i] + rb[i] + cb[j] )
// Tiles: 64x64 output, BK=32, 256 threads, 4x4 micro-tile.
// ---------------------------------------------------------------------------
#define BM 64
#define BN 64
#define BK 32

__global__ __launch_bounds__(256) void gemm_ep(
    const float* __restrict__ A, const float* __restrict__ B, float* __restrict__ C,
    int K, int lda, int ldb, int ldc,
    const float* __restrict__ rs, const float* __restrict__ rb,
    const float* __restrict__ cb, int do_relu)
{
    __shared__ float As[BK][BM + 1];   // A tile, transposed (k-major)
    __shared__ float Bs[BK][BN];

    const int tid = threadIdx.x;
    const int tx = tid & 15;          // 16 col groups
    const int ty = tid >> 4;          // 16 row groups
    const int row0 = blockIdx.y * BM;
    const int col0 = blockIdx.x * BN;

    float acc[4][4];
#pragma unroll
    for (int i = 0; i < 4; i++)
#pragma unroll
        for (int j = 0; j < 4; j++) acc[i][j] = 0.0f;

    for (int k0 = 0; k0 < K; k0 += BK) {
        // Stage A tile (BM x BK) transposed into As
#pragma unroll
        for (int l = 0; l < 2; l++) {
            int idx = tid + l * 256;          // 0..511
            int r = idx >> 3;                 // row in tile
            int kg = (idx & 7) << 2;          // k group *4
            float4 v = *reinterpret_cast<const float4*>(
                A + (size_t)(row0 + r) * lda + k0 + kg);
            As[kg + 0][r] = v.x;
            As[kg + 1][r] = v.y;
            As[kg + 2][r] = v.z;
            As[kg + 3][r] = v.w;
        }
        // Stage B tile (BK x BN)
#pragma unroll
        for (int l = 0; l < 2; l++) {
            int idx = tid + l * 256;
            int r = idx >> 4;
            int cg = (idx & 15) << 2;
            *reinterpret_cast<float4*>(&Bs[r][cg]) =
                *reinterpret_cast<const float4*>(B + (size_t)(k0 + r) * ldb + col0 + cg);
        }
        __syncthreads();

#pragma unroll
        for (int kk = 0; kk < BK; kk++) {
            float a0 = As[kk][ty * 4 + 0];
            float a1 = As[kk][ty * 4 + 1];
            float a2 = As[kk][ty * 4 + 2];
            float a3 = As[kk][ty * 4 + 3];
            float4 bv = *reinterpret_cast<const float4*>(&Bs[kk][tx * 4]);
            acc[0][0] = fmaf(a0, bv.x, acc[0][0]);
            acc[0][1] = fmaf(a0, bv.y, acc[0][1]);
            acc[0][2] = fmaf(a0, bv.z, acc[0][2]);
            acc[0][3] = fmaf(a0, bv.w, acc[0][3]);
            acc[1][0] = fmaf(a1, bv.x, acc[1][0]);
            acc[1][1] = fmaf(a1, bv.y, acc[1][1]);
            acc[1][2] = fmaf(a1, bv.z, acc[1][2]);
            acc[1][3] = fmaf(a1, bv.w, acc[1][3]);
            acc[2][0] = fmaf(a2, bv.x, acc[2][0]);
            acc[2][1] = fmaf(a2, bv.y, acc[2][1]);
            acc[2][2] = fmaf(a2, bv.z, acc[2][2]);
            acc[2][3] = fmaf(a2, bv.w, acc[2][3]);
            acc[3][0] = fmaf(a3, bv.x, acc[3][0]);
            acc[3][1] = fmaf(a3, bv.y, acc[3][1]);
            acc[3][2] = fmaf(a3, bv.z, acc[3][2]);
            acc[3][3] = fmaf(a3, bv.w, acc[3][3]);
        }
        __syncthreads();
    }

#pragma unroll
    for (int ii = 0; ii < 4; ii++) {
        int i = row0 + ty * 4 + ii;
        float s = rs ? rs[i] : 1.0f;
        float rbv = rb ? rb[i] : 0.0f;
        float4 out;
        float* o = &out.x;
#pragma unroll
        for (int jj = 0; jj < 4; jj++) {
            int j = col0 + tx * 4 + jj;
            float v = acc[ii][jj] * s + rbv + (cb ? cb[j] : 0.0f);
            if (do_relu) v = fmaxf(v, 0.0f);
            o[jj] = v;
        }
        *reinterpret_cast<float4*>(C + (size_t)i * ldc + col0 + tx * 4) = out;
    }
}

// ---------------------------------------------------------------------------
// Symmetric P = sigmoid(U @ U^T) over upper-triangular 64x64 tile pairs,
// mirroring each off-diagonal tile. U is [n, 128] row-major.
// Writes into P with row/col offset `off`, leading dim ldp.
// ---------------------------------------------------------------------------
__global__ __launch_bounds__(256) void xxt_sigmoid(
    const float* __restrict__ U, int n, float* __restrict__ P, int ldp, int off)
{
    __shared__ float It[BK][BM + 1];
    __shared__ float Jt[BK][BM + 1];

    int b = blockIdx.x;
    // map linear pair index -> (bi <= bj)
    int bj = (int)((sqrtf(8.0f * (float)b + 1.0f) - 1.0f) * 0.5f);
    while ((bj + 1) * (bj + 2) / 2 <= b) bj++;
    while (bj * (bj + 1) / 2 > b) bj--;
    int bi = b - bj * (bj + 1) / 2;

    const int tid = threadIdx.x;
    const int tx = tid & 15;
    const int ty = tid >> 4;

    float acc[4][4];
#pragma unroll
    for (int i = 0; i < 4; i++)
#pragma unroll
        for (int j = 0; j < 4; j++) acc[i][j] = 0.0f;

    for (int k0 = 0; k0 < DIM; k0 += BK) {
#pragma unroll
        for (int l = 0; l < 2; l++) {
            int idx = tid + l * 256;
            int r = idx >> 3;
            int kg = (idx & 7) << 2;
            float4 v = *reinterpret_cast<const float4*>(
                U + (size_t)(bi * 64 + r) * DIM + k0 + kg);
            It[kg + 0][r] = v.x;
            It[kg + 1][r] = v.y;
            It[kg + 2][r] = v.z;
            It[kg + 3][r] = v.w;
            float4 w = *reinterpret_cast<const float4*>(
                U + (size_t)(bj * 64 + r) * DIM + k0 + kg);
            Jt[kg + 0][r] = w.x;
            Jt[kg + 1][r] = w.y;
            Jt[kg + 2][r] = w.z;
            Jt[kg + 3][r] = w.w;
        }
        __syncthreads();
#pragma unroll
        for (int kk = 0; kk < BK; kk++) {
            float a0 = It[kk][ty * 4 + 0];
            float a1 = It[kk][ty * 4 + 1];
            float a2 = It[kk][ty * 4 + 2];
            float a3 = It[kk][ty * 4 + 3];
            float b0 = Jt[kk][tx * 4 + 0];
            float b1 = Jt[kk][tx * 4 + 1];
            float b2 = Jt[kk][tx * 4 + 2];
            float b3 = Jt[kk][tx * 4 + 3];
            acc[0][0] = fmaf(a0, b0, acc[0][0]);
            acc[0][1] = fmaf(a0, b1, acc[0][1]);
            acc[0][2] = fmaf(a0, b2, acc[0][2]);
            acc[0][3] = fmaf(a0, b3, acc[0][3]);
            acc[1][0] = fmaf(a1, b0, acc[1][0]);
            acc[1][1] = fmaf(a1, b1, acc[1][1]);
            acc[1][2] = fmaf(a1, b2, acc[1][2]);
            acc[1][3] = fmaf(a1, b3, acc[1][3]);
            acc[2][0] = fmaf(a2, b0, acc[2][0]);
            acc[2][1] = fmaf(a2, b1, acc[2][1]);
            acc[2][2] = fmaf(a2, b2, acc[2][2]);
            acc[2][3] = fmaf(a2, b3, acc[2][3]);
            acc[3][0] = fmaf(a3, b0, acc[3][0]);
            acc[3][1] = fmaf(a3, b1, acc[3][1]);
            acc[3][2] = fmaf(a3, b2, acc[3][2]);
            acc[3][3] = fmaf(a3, b3, acc[3][3]);
        }
        __syncthreads();
    }

    float sv[4][4];
#pragma unroll
    for (int ii = 0; ii < 4; ii++)
#pragma unroll
        for (int jj = 0; jj < 4; jj++)
            sv[ii][jj] = 1.0f / (1.0f + expf(-acc[ii][jj]));

    const int gi0 = off + bi * 64 + ty * 4;
    const int gj0 = off + bj * 64 + tx * 4;
#pragma unroll
    for (int ii = 0; ii < 4; ii++) {
        float4 out = make_float4(sv[ii][0], sv[ii][1], sv[ii][2], sv[ii][3]);
        *reinterpret_cast<float4*>(P + (size_t)(gi0 + ii) * ldp + gj0) = out;
    }
    if (bi != bj) {
#pragma unroll
        for (int jj = 0; jj < 4; jj++) {
            float4 out = make_float4(sv[0][jj], sv[1][jj], sv[2][jj], sv[3][jj]);
            *reinterpret_cast<float4*>(P + (size_t)(gj0 + jj) * ldp + gi0) = out;
        }
    }
}

// ---------------------------------------------------------------------------
// dinv[i] = rsqrt(sum_j P[i,j])  (P is symmetric: row sum == column sum)
// ---------------------------------------------------------------------------
__global__ __launch_bounds__(256) void deg_kernel(
    const float* __restrict__ P, float* __restrict__ dinv, int m)
{
    __shared__ float red[256];
    const int row = blockIdx.x;
    const float4* p = reinterpret_cast<const float4*>(P + (size_t)row * m);
    float s = 0.0f;
    for (int j = threadIdx.x; j < (m >> 2); j += 256) {
        float4 v = p[j];
        s += (v.x + v.y) + (v.z + v.w);
    }
    red[threadIdx.x] = s;
    __syncthreads();
    for (int st = 128; st > 0; st >>= 1) {
        if (threadIdx.x < st) red[threadIdx.x] += red[threadIdx.x + st];
        __syncthreads();
    }
    if (threadIdx.x == 0) {
        float d = red[0];
        dinv[row] = d > 0.0f ? rsqrtf(d) : 0.0f;
    }
}

// ---------------------------------------------------------------------------
// Initial block adjacency: P[:N,:N] = A, P[:N,N:] = A^T (== A, bitwise
// symmetric since A = 0.5*(R+R^T)), P[N:,:N] = A. Bottom-right filled by xxt.
// ---------------------------------------------------------------------------
__global__ __launch_bounds__(256) void build_blocks(
    const float* __restrict__ A, float* __restrict__ P)
{
    const int total = N_NODES * (N_NODES / 4);
    int idx = blockIdx.x * 256 + threadIdx.x;
    if (idx >= total) return;
    int i = idx / (N_NODES / 4);
    int j4 = idx % (N_NODES / 4);
    float4 v = reinterpret_cast<const float4*>(A)[(size_t)i * (N_NODES / 4) + j4];
    reinterpret_cast<float4*>(P + (size_t)i * M_NODES)[j4] = v;
    reinterpret_cast<float4*>(P + (size_t)i * M_NODES + N_NODES)[j4] = v;
    reinterpret_cast<float4*>(P + (size_t)(i + N_NODES) * M_NODES)[j4] = v;
}

// ---------------------------------------------------------------------------

extern "C" void kernel_launch(void* const* d_in, const int* in_sizes, int n_in,
                              void* d_out, int out_size)
{
    const float* X   = (const float*)d_in[0];
    const float* A   = (const float*)d_in[1];
    const float* Wup = (const float*)d_in[2];
    const float* bup = (const float*)d_in[3];
    const float* W1  = (const float*)d_in[4];
    const float* b1  = (const float*)d_in[5];
    const float* W2  = (const float*)d_in[6];
    const float* b2  = (const float*)d_in[7];
    float* P = (float*)d_out;   // Adj lives in d_out the whole time

    float *Xu, *Y, *dinv;
    cudaGetSymbolAddress((void**)&Xu, g_Xu);
    cudaGetSymbolAddress((void**)&Y, g_Y);
    cudaGetSymbolAddress((void**)&dinv, g_dinv);

    // Xu[0:N] = X
    cudaMemcpyAsync(Xu, X, (size_t)N_NODES * DIM * sizeof(float),
                    cudaMemcpyDeviceToDevice);

    // Xu[N:M] = new_nodes = W_up @ X + b_up
    {
        dim3 g(DIM / BN, N_NODES / BM);
        gemm_ep<<<g, 256>>>(Wup, X, Xu + (size_t)N_NODES * DIM,
                            N_NODES, N_NODES, DIM, DIM,
                            nullptr, bup, nullptr, 0);
    }

    // Block adjacency into P
    build_blocks<<<(N_NODES * (N_NODES / 4) + 255) / 256, 256>>>(A, P);
    {
        int T = N_NODES / 64;
        xxt_sigmoid<<<T * (T + 1) / 2, 256>>>(Xu + (size_t)N_NODES * DIM,
                                              N_NODES, P, M_NODES, N_NODES);
    }

    dim3 gbig(DIM / BN, M_NODES / BM);   // 2 x 128 = 256 blocks
    for (int it = 0; it < NUM_ITERS; it++) {
        // conv1
        deg_kernel<<<M_NODES, 256>>>(P, dinv, M_NODES);
        gemm_ep<<<gbig, 256>>>(Xu, W1, Y, DIM, DIM, DIM, DIM,
                               dinv, nullptr, nullptr, 0);        // Y = dinv .* (Xu@W1)
        gemm_ep<<<gbig, 256>>>(P, Y, Xu, M_NODES, M_NODES, DIM, DIM,
                               dinv, nullptr, b1, 1);             // Xu = relu(dinv.*(P@Y)+b1)
        // Adj = sigmoid(Xu Xu^T)
        {
            int T = M_NODES / 64;
            xxt_sigmoid<<<T * (T + 1) / 2, 256>>>(Xu, M_NODES, P, M_NODES, 0);
        }
        // conv2
        deg_kernel<<<M_NODES, 256>>>(P, dinv, M_NODES);
        gemm_ep<<<gbig, 256>>>(Xu, W2, Y, DIM, DIM, DIM, DIM,
                               dinv, nullptr, nullptr, 0);
        gemm_ep<<<gbig, 256>>>(P, Y, Xu, M_NODES, M_NODES, DIM, DIM,
                               dinv, nullptr, b2, 1);
        // A_out of iters 0,1 is dead (loop uses the mid-loop Adj) — skip it.
    }

    // Final A_out = sigmoid(Xu Xu^T) written straight into d_out
    {
        int T = M_NODES / 64;
        xxt_sigmoid<<<T * (T + 1) / 2, 256>>>(Xu, M_NODES, P, M_NODES, 0);
    }
    (void)in_sizes; (void)n_in; (void)out_size;
}

// round 4
// speedup vs baseline: 3.3604x; 3.3604x over previous
#include <cuda_runtime.h>
#include <cuda_bf16.h>
#include <stdint.h>
#include <math.h>

#define NN 4096
#define MM 8192
#define DD 128

typedef __nv_bfloat16 bf16;

// ----------------- device scratch (no allocations allowed) -----------------
__device__ bf16  g_Phi[(size_t)MM * MM];
__device__ bf16  g_Plo[(size_t)MM * MM];
__device__ bf16  g_Xuh[MM * DD];
__device__ bf16  g_Xul[MM * DD];
__device__ bf16  g_Yth[DD * MM];
__device__ bf16  g_Ytl[DD * MM];
__device__ bf16  g_Xth[DD * NN];
__device__ bf16  g_Xtl[DD * NN];
__device__ bf16  g_W1h[DD * DD];
__device__ bf16  g_W1l[DD * DD];
__device__ bf16  g_W2h[DD * DD];
__device__ bf16  g_W2l[DD * DD];
__device__ bf16  g_Wuh[(size_t)NN * NN];
__device__ bf16  g_Wul[(size_t)NN * NN];
__device__ float g_part[2 * MM * DD];
__device__ float g_dinv[MM];

// ----------------------------- helpers ------------------------------------
__device__ __forceinline__ uint32_t s2u(const void* p) {
    uint32_t a;
    asm("{ .reg .u64 t; cvta.to.shared.u64 t, %1; cvt.u32.u64 %0, t; }"
        : "=r"(a) : "l"(p));
    return a;
}
#define SW128(o) ((o) ^ (((o) >> 3) & 0x70))

#define CPA(dst, src) asm volatile( \
    "cp.async.cg.shared.global [%0], [%1], 16;" :: "r"(dst), "l"(src))
#define CPCOMMIT() asm volatile("cp.async.commit_group;" ::: "memory")
#define CPWAIT(n)  asm volatile("cp.async.wait_group %0;" :: "n"(n) : "memory")

__device__ __forceinline__ void ldmx4(uint32_t* r, uint32_t a) {
    asm volatile("ldmatrix.sync.aligned.m8n8.x4.shared.b16 {%0,%1,%2,%3}, [%4];"
        : "=r"(r[0]), "=r"(r[1]), "=r"(r[2]), "=r"(r[3]) : "r"(a));
}
__device__ __forceinline__ void ldmx2(uint32_t* r, uint32_t a) {
    asm volatile("ldmatrix.sync.aligned.m8n8.x2.shared.b16 {%0,%1}, [%2];"
        : "=r"(r[0]), "=r"(r[1]) : "r"(a));
}
__device__ __forceinline__ void mma16816(float* c, const uint32_t* a, const uint32_t* b) {
    asm volatile(
        "mma.sync.aligned.m16n8k16.row.col.f32.bf16.bf16.f32 "
        "{%0,%1,%2,%3}, {%4,%5,%6,%7}, {%8,%9}, {%0,%1,%2,%3};"
        : "+f"(c[0]), "+f"(c[1]), "+f"(c[2]), "+f"(c[3])
        : "r"(a[0]), "r"(a[1]), "r"(a[2]), "r"(a[3]), "r"(b[0]), "r"(b[1]));
}

// hi/lo split packing
__device__ __forceinline__ uint32_t pk2(float a, float b, uint32_t& lo) {
    bf16 ha = __float2bfloat16(a), hb = __float2bfloat16(b);
    bf16 la = __float2bfloat16(a - __bfloat162float(ha));
    bf16 lb = __float2bfloat16(b - __bfloat162float(hb));
    lo = ((uint32_t)__bfloat16_as_ushort(lb) << 16) | __bfloat16_as_ushort(la);
    return ((uint32_t)__bfloat16_as_ushort(hb) << 16) | __bfloat16_as_ushort(ha);
}
__device__ __forceinline__ uint32_t pk1(float a) {
    bf16 h = __float2bfloat16(a);
    bf16 l = __float2bfloat16(a - __bfloat162float(h));
    return (uint32_t)__bfloat16_as_ushort(h) | ((uint32_t)__bfloat16_as_ushort(l) << 16);
}
__device__ __forceinline__ float sigm(float x) {
    return __fdividef(1.0f, 1.0f + __expf(-x));
}

#define ADJ_SMEM 131072   // 2 stages x (4 mats x 16KB)
#define XXT_SMEM 131072   // 4 mats x 32KB (reused for epilogue staging)

// ===========================================================================
// adj_mul_mma: part[y] = A @ B^T,  A [M x K] hi/lo row-major (lda),
// B [128 x K] hi/lo row-major (ldb). grid(x = M/128, y = ksplit).
// CTA 128x128, BK=64, 8 warps (2M x 4N) of 64x32, double-buffered cp.async.
// ===========================================================================
__device__ __forceinline__ void adj_load(uint32_t sb, uint32_t stage,
    const bf16* Ah, const bf16* Al, int lda,
    const bf16* Bh, const bf16* Bl, int ldb, int m0, int k0, int tid)
{
    uint32_t base = sb + stage * 65536u;
#pragma unroll
    for (int p = 0; p < 16; p++) {
        int idx = tid + p * 256;
        int mat = idx >> 10, w = idx & 1023, r = w >> 3, cg = w & 7;
        const bf16* s;
        if      (mat == 0) s = Ah + (size_t)(m0 + r) * lda + k0 + cg * 8;
        else if (mat == 1) s = Al + (size_t)(m0 + r) * lda + k0 + cg * 8;
        else if (mat == 2) s = Bh + (size_t)r * ldb + k0 + cg * 8;
        else               s = Bl + (size_t)r * ldb + k0 + cg * 8;
        CPA(base + mat * 16384u + SW128(r * 128 + cg * 16), s);
    }
}

__global__ __launch_bounds__(256, 1) void adj_mul_mma(
    const bf16* __restrict__ Ah, const bf16* __restrict__ Al, int lda,
    const bf16* __restrict__ Bh, const bf16* __restrict__ Bl, int ldb,
    float* __restrict__ part, int kcta, int pstride)
{
    extern __shared__ char smem[];
    const uint32_t sb = s2u(smem);
    const int tid = threadIdx.x, wid = tid >> 5, lane = tid & 31;
    const int wm = wid & 1, wn = wid >> 1;
    const int m0 = blockIdx.x * 128;
    const int k0b = blockIdx.y * kcta;
    const int NT = kcta >> 6;

    float acc[4][4][4];
#pragma unroll
    for (int i = 0; i < 4; i++)
#pragma unroll
        for (int j = 0; j < 4; j++)
#pragma unroll
            for (int e = 0; e < 4; e++) acc[i][j][e] = 0.0f;

    // per-lane ldmatrix offset pieces
    const uint32_t swz = (uint32_t)(lane & 7) << 4;
    uint32_t arow[4], brow[4];
#pragma unroll
    for (int t = 0; t < 4; t++) {
        arow[t] = (uint32_t)((wm * 64 + t * 16 + (lane & 15)) * 128);
        brow[t] = (uint32_t)((wn * 32 + t * 8 + (lane & 7)) * 128);
    }
    const uint32_t akh = (uint32_t)((lane >> 4) * 16);
    const uint32_t bkh = (uint32_t)(((lane >> 3) & 1) * 16);

    adj_load(sb, 0, Ah, Al, lda, Bh, Bl, ldb, m0, k0b, tid);
    CPCOMMIT();

    for (int kt = 0; kt < NT; kt++) {
        if (kt + 1 < NT) {
            adj_load(sb, (kt + 1) & 1, Ah, Al, lda, Bh, Bl, ldb,
                     m0, k0b + (kt + 1) * 64, tid);
            CPCOMMIT();
            CPWAIT(1);
        } else {
            CPWAIT(0);
        }
        __syncthreads();

        uint32_t st = sb + (uint32_t)(kt & 1) * 65536u;
#pragma unroll
        for (int ks = 0; ks < 4; ks++) {
            uint32_t axk = ((uint32_t)(ks * 32) + akh) ^ swz;
            uint32_t bxk = ((uint32_t)(ks * 32) + bkh) ^ swz;
            uint32_t ah[4][4], al[4][4], bh[4][2], bl[4][2];
#pragma unroll
            for (int t = 0; t < 4; t++) {
                ldmx4(ah[t], st + arow[t] + axk);
                ldmx4(al[t], st + 16384u + arow[t] + axk);
                ldmx2(bh[t], st + 32768u + brow[t] + bxk);
                ldmx2(bl[t], st + 49152u + brow[t] + bxk);
            }
#pragma unroll
            for (int tm = 0; tm < 4; tm++)
#pragma unroll
                for (int tn = 0; tn < 4; tn++) {
                    mma16816(acc[tm][tn], ah[tm], bh[tn]);
                    mma16816(acc[tm][tn], al[tm], bh[tn]);
                    mma16816(acc[tm][tn], ah[tm], bl[tn]);
                }
        }
        __syncthreads();
    }

    float* dst = part + (size_t)blockIdx.y * pstride + (size_t)m0 * 128;
#pragma unroll
    for (int tm = 0; tm < 4; tm++)
#pragma unroll
        for (int tn = 0; tn < 4; tn++) {
            int r0 = wm * 64 + tm * 16 + (lane >> 2);
            int c0 = wn * 32 + tn * 8 + 2 * (lane & 3);
            *(float2*)(dst + (size_t)r0 * 128 + c0) =
                make_float2(acc[tm][tn][0], acc[tm][tn][1]);
            *(float2*)(dst + (size_t)(r0 + 8) * 128 + c0) =
                make_float2(acc[tm][tn][2], acc[tm][tn][3]);
        }
}

// ===========================================================================
// xxt_mma: sigmoid(X X^T) over upper-tri 128x128 tile pairs (X hi/lo, K=128).
// mode 0: bf16 hi/lo into Ph/Pl (+mirror).  mode 1: fp32 into Pf (+mirror).
// ===========================================================================
__global__ __launch_bounds__(256, 1) void xxt_mma(
    const bf16* __restrict__ Xh, const bf16* __restrict__ Xl, int ooff,
    bf16* __restrict__ Ph, bf16* __restrict__ Pl, float* __restrict__ Pf, int mode)
{
    extern __shared__ char smem[];
    const uint32_t sb = s2u(smem);
    const int tid = threadIdx.x, wid = tid >> 5, lane = tid & 31;
    const int wm = wid & 1, wn = wid >> 1;

    int b = blockIdx.x;
    int bj = (int)((sqrtf(8.0f * (float)b + 1.0f) - 1.0f) * 0.5f);
    while ((bj + 1) * (bj + 2) / 2 <= b) bj++;
    while (bj * (bj + 1) / 2 > b) bj--;
    int bi = b - bj * (bj + 1) / 2;

    // load Ih, Il, Jh, Jl: each [128 x 128] bf16 as 2 SW128 64-col halves
#pragma unroll
    for (int p = 0; p < 32; p++) {
        int idx = tid + p * 256;
        int mat = idx >> 11, w = idx & 2047, kb = w >> 10, ww = w & 1023;
        int r = ww >> 3, cg = ww & 7;
        const bf16* base = (mat & 1) ? Xl : Xh;
        int rb = ((mat < 2) ? bi : bj) * 128;
        CPA(sb + (uint32_t)mat * 32768u + (uint32_t)kb * 16384u +
                SW128(r * 128 + cg * 16),
            base + (size_t)(rb + r) * 128 + kb * 64 + cg * 8);
    }
    CPCOMMIT();

    float acc[4][4][4];
#pragma unroll
    for (int i = 0; i < 4; i++)
#pragma unroll
        for (int j = 0; j < 4; j++)
#pragma unroll
            for (int e = 0; e < 4; e++) acc[i][j][e] = 0.0f;

    const uint32_t swz = (uint32_t)(lane & 7) << 4;
    uint32_t arow[4], brow[4];
#pragma unroll
    for (int t = 0; t < 4; t++) {
        arow[t] = (uint32_t)((wm * 64 + t * 16 + (lane & 15)) * 128);
        brow[t] = (uint32_t)((wn * 32 + t * 8 + (lane & 7)) * 128);
    }
    const uint32_t akh = (uint32_t)((lane >> 4) * 16);
    const uint32_t bkh = (uint32_t)(((lane >> 3) & 1) * 16);

    CPWAIT(0);
    __syncthreads();

#pragma unroll
    for (int ks = 0; ks < 8; ks++) {
        uint32_t kbo = (uint32_t)(ks >> 2) * 16384u;
        uint32_t axk = ((uint32_t)((ks & 3) * 32) + akh) ^ swz;
        uint32_t bxk = ((uint32_t)((ks & 3) * 32) + bkh) ^ swz;
        uint32_t ah[4][4], al[4][4], bh[4][2], bl[4][2];
#pragma unroll
        for (int t = 0; t < 4; t++) {
            ldmx4(ah[t], sb + kbo + arow[t] + axk);
            ldmx4(al[t], sb + 32768u + kbo + arow[t] + axk);
            ldmx2(bh[t], sb + 65536u + kbo + brow[t] + bxk);
            ldmx2(bl[t], sb + 98304u + kbo + brow[t] + bxk);
        }
#pragma unroll
        for (int tm = 0; tm < 4; tm++)
#pragma unroll
            for (int tn = 0; tn < 4; tn++) {
                mma16816(acc[tm][tn], ah[tm], bh[tn]);
                mma16816(acc[tm][tn], al[tm], bh[tn]);
                mma16816(acc[tm][tn], ah[tm], bl[tn]);
            }
    }
    __syncthreads();   // tiles consumed; smem reusable for staging

    const int gi0 = ooff + bi * 128;
    const int gj0 = ooff + bj * 128;

    if (mode == 0) {
        uint32_t* sm = (uint32_t*)smem;   // [128][133]
#pragma unroll
        for (int tm = 0; tm < 4; tm++)
#pragma unroll
            for (int tn = 0; tn < 4; tn++) {
                int r0 = wm * 64 + tm * 16 + (lane >> 2);
                int c0 = wn * 32 + tn * 8 + 2 * (lane & 3);
                sm[r0 * 133 + c0]       = pk1(sigm(acc[tm][tn][0]));
                sm[r0 * 133 + c0 + 1]   = pk1(sigm(acc[tm][tn][1]));
                sm[(r0 + 8) * 133 + c0]     = pk1(sigm(acc[tm][tn][2]));
                sm[(r0 + 8) * 133 + c0 + 1] = pk1(sigm(acc[tm][tn][3]));
            }
        __syncthreads();

        int r = tid >> 1, cbase = (tid & 1) * 64;
#pragma unroll
        for (int c8 = 0; c8 < 8; c8++) {
            int cb = cbase + c8 * 8;
            uint32_t q[8];
#pragma unroll
            for (int e = 0; e < 8; e++) q[e] = sm[r * 133 + cb + e];
            uint4 hv, lv;
            hv.x = (q[0] & 0xffffu) | (q[1] << 16);
            lv.x = (q[0] >> 16) | (q[1] & 0xffff0000u);
            hv.y = (q[2] & 0xffffu) | (q[3] << 16);
            lv.y = (q[2] >> 16) | (q[3] & 0xffff0000u);
            hv.z = (q[4] & 0xffffu) | (q[5] << 16);
            lv.z = (q[4] >> 16) | (q[5] & 0xffff0000u);
            hv.w = (q[6] & 0xffffu) | (q[7] << 16);
            lv.w = (q[6] >> 16) | (q[7] & 0xffff0000u);
            *(uint4*)(Ph + (size_t)(gi0 + r) * MM + gj0 + cb) = hv;
            *(uint4*)(Pl + (size_t)(gi0 + r) * MM + gj0 + cb) = lv;
        }
        if (bi != bj) {
#pragma unroll
            for (int c8 = 0; c8 < 8; c8++) {
                int cb = cbase + c8 * 8;
                uint32_t q[8];
#pragma unroll
                for (int e = 0; e < 8; e++) q[e] = sm[(cb + e) * 133 + r];
                uint4 hv, lv;
                hv.x = (q[0] & 0xffffu) | (q[1] << 16);
                lv.x = (q[0] >> 16) | (q[1] & 0xffff0000u);
                hv.y = (q[2] & 0xffffu) | (q[3] << 16);
                lv.y = (q[2] >> 16) | (q[3] & 0xffff0000u);
                hv.z = (q[4] & 0xffffu) | (q[5] << 16);
                lv.z = (q[4] >> 16) | (q[5] & 0xffff0000u);
                hv.w = (q[6] & 0xffffu) | (q[7] << 16);
                lv.w = (q[6] >> 16) | (q[7] & 0xffff0000u);
                *(uint4*)(Ph + (size_t)(gj0 + r) * MM + gi0 + cb) = hv;
                *(uint4*)(Pl + (size_t)(gj0 + r) * MM + gi0 + cb) = lv;
            }
        }
    } else {
        float* sf = (float*)smem;   // [128][133]
#pragma unroll
        for (int tm = 0; tm < 4; tm++)
#pragma unroll
            for (int tn = 0; tn < 4; tn++) {
                int r0 = wm * 64 + tm * 16 + (lane >> 2);
                int c0 = wn * 32 + tn * 8 + 2 * (lane & 3);
                sf[r0 * 133 + c0]       = sigm(acc[tm][tn][0]);
                sf[r0 * 133 + c0 + 1]   = sigm(acc[tm][tn][1]);
                sf[(r0 + 8) * 133 + c0]     = sigm(acc[tm][tn][2]);
                sf[(r0 + 8) * 133 + c0 + 1] = sigm(acc[tm][tn][3]);
            }
        __syncthreads();

        int r = tid >> 1, cbase = (tid & 1) * 64;
#pragma unroll
        for (int c4 = 0; c4 < 16; c4++) {
            int cb = cbase + c4 * 4;
            float4 o = make_float4(sf[r * 133 + cb], sf[r * 133 + cb + 1],
                                   sf[r * 133 + cb + 2], sf[r * 133 + cb + 3]);
            *(float4*)(Pf + (size_t)(gi0 + r) * MM + gj0 + cb) = o;
        }
        if (bi != bj) {
#pragma unroll
            for (int c4 = 0; c4 < 16; c4++) {
                int cb = cbase + c4 * 4;
                float4 o = make_float4(sf[(cb + 0) * 133 + r], sf[(cb + 1) * 133 + r],
                                       sf[(cb + 2) * 133 + r], sf[(cb + 3) * 133 + r]);
                *(float4*)(Pf + (size_t)(gj0 + r) * MM + gi0 + cb) = o;
            }
        }
    }
}

// ------------------------ small elementwise kernels ------------------------
__global__ __launch_bounds__(256) void deg_hi(const bf16* __restrict__ Ph,
                                              float* __restrict__ dinv)
{
    __shared__ float red[256];
    const uint4* p = (const uint4*)(Ph + (size_t)blockIdx.x * MM);
    float s = 0.0f;
    for (int j = threadIdx.x; j < 1024; j += 256) {
        uint4 u = p[j];
        float2 a = __bfloat1622float2(*(__nv_bfloat162*)&u.x);
        float2 b = __bfloat1622float2(*(__nv_bfloat162*)&u.y);
        float2 c = __bfloat1622float2(*(__nv_bfloat162*)&u.z);
        float2 d = __bfloat1622float2(*(__nv_bfloat162*)&u.w);
        s += (a.x + a.y) + (b.x + b.y) + (c.x + c.y) + (d.x + d.y);
    }
    red[threadIdx.x] = s;
    __syncthreads();
    for (int st = 128; st > 0; st >>= 1) {
        if (threadIdx.x < st) red[threadIdx.x] += red[threadIdx.x + st];
        __syncthreads();
    }
    if (threadIdx.x == 0)
        dinv[blockIdx.x] = red[0] > 0.0f ? rsqrtf(red[0]) : 0.0f;
}

__global__ __launch_bounds__(256) void cvt4(const float* __restrict__ s,
                                            bf16* __restrict__ dh, bf16* __restrict__ dl, int n4)
{
    int i = blockIdx.x * 256 + threadIdx.x;
    if (i >= n4) return;
    float4 v = ((const float4*)s)[i];
    uint2 h, l;
    h.x = pk2(v.x, v.y, l.x);
    h.y = pk2(v.z, v.w, l.y);
    ((uint2*)dh)[i] = h;
    ((uint2*)dl)[i] = l;
}

__global__ void tcvt(const float* __restrict__ src, bf16* __restrict__ dh,
                     bf16* __restrict__ dl, int R, int C)
{
    __shared__ float t[32][33];
    int c0 = blockIdx.x * 32, r0 = blockIdx.y * 32;
    for (int i = threadIdx.y; i < 32; i += 8)
        t[i][threadIdx.x] = src[(size_t)(r0 + i) * C + c0 + threadIdx.x];
    __syncthreads();
    for (int i = threadIdx.y; i < 32; i += 8) {
        float v = t[threadIdx.x][i];
        bf16 h = __float2bfloat16(v);
        dh[(size_t)(c0 + i) * R + r0 + threadIdx.x] = h;
        dl[(size_t)(c0 + i) * R + r0 + threadIdx.x] =
            __float2bfloat16(v - __bfloat162float(h));
    }
}

__global__ void ytrans(const float* __restrict__ part, const float* __restrict__ dinv,
                       bf16* __restrict__ yh, bf16* __restrict__ yl)
{
    __shared__ float t[32][33];
    int j0 = blockIdx.x * 32, c0 = blockIdx.y * 32;
    for (int i = threadIdx.y; i < 32; i += 8)
        t[i][threadIdx.x] = part[(size_t)(j0 + i) * 128 + c0 + threadIdx.x] * dinv[j0 + i];
    __syncthreads();
    for (int i = threadIdx.y; i < 32; i += 8) {
        float v = t[threadIdx.x][i];
        bf16 h = __float2bfloat16(v);
        yh[(size_t)(c0 + i) * MM + j0 + threadIdx.x] = h;
        yl[(size_t)(c0 + i) * MM + j0 + threadIdx.x] =
            __float2bfloat16(v - __bfloat162float(h));
    }
}

__global__ __launch_bounds__(256) void xcombine(const float* __restrict__ part,
    const float* __restrict__ dinv, const float* __restrict__ bias,
    bf16* __restrict__ xh, bf16* __restrict__ xl)
{
    int idx = blockIdx.x * 256 + threadIdx.x;
    int base = idx * 4, row = base >> 7, c = base & 127;
    float4 a = ((const float4*)part)[idx];
    float4 b = ((const float4*)(part + MM * DD))[idx];
    float di = dinv[row];
    float v0 = fmaxf(di * (a.x + b.x) + bias[c + 0], 0.0f);
    float v1 = fmaxf(di * (a.y + b.y) + bias[c + 1], 0.0f);
    float v2 = fmaxf(di * (a.z + b.z) + bias[c + 2], 0.0f);
    float v3 = fmaxf(di * (a.w + b.w) + bias[c + 3], 0.0f);
    uint2 h, l;
    h.x = pk2(v0, v1, l.x);
    h.y = pk2(v2, v3, l.y);
    ((uint2*)xh)[idx] = h;
    ((uint2*)xl)[idx] = l;
}

__global__ __launch_bounds__(256) void up_combine(const float* __restrict__ part,
    const float* __restrict__ bup, bf16* __restrict__ xh, bf16* __restrict__ xl)
{
    int idx = blockIdx.x * 256 + threadIdx.x;
    int base = idx * 4, row = base >> 7;
    float4 a = ((const float4*)part)[idx];
    float4 b = ((const float4*)(part + MM * DD))[idx];
    float bu = bup[row];
    uint2 h, l;
    h.x = pk2(a.x + b.x + bu, a.y + b.y + bu, l.x);
    h.y = pk2(a.z + b.z + bu, a.w + b.w + bu, l.y);
    ((uint2*)(xh + (size_t)NN * DD))[idx] = h;
    ((uint2*)(xl + (size_t)NN * DD))[idx] = l;
}

__global__ __launch_bounds__(256) void buildA(const float* __restrict__ A,
                                              bf16* __restrict__ Ph, bf16* __restrict__ Pl)
{
    int idx = blockIdx.x * 256 + threadIdx.x;
    int i = idx >> 10, j4 = idx & 1023;
    float4 v = ((const float4*)A)[(size_t)i * 1024 + j4];
    uint2 h, l;
    h.x = pk2(v.x, v.y, l.x);
    h.y = pk2(v.z, v.w, l.y);
    size_t o0 = (size_t)i * MM + j4 * 4;
    size_t o1 = o0 + NN;
    size_t o2 = (size_t)(i + NN) * MM + j4 * 4;
    *(uint2*)(Ph + o0) = h; *(uint2*)(Pl + o0) = l;
    *(uint2*)(Ph + o1) = h; *(uint2*)(Pl + o1) = l;
    *(uint2*)(Ph + o2) = h; *(uint2*)(Pl + o2) = l;
}

// ---------------------------------------------------------------------------
extern "C" void kernel_launch(void* const* d_in, const int* in_sizes, int n_in,
                              void* d_out, int out_size)
{
    const float* X   = (const float*)d_in[0];
    const float* A   = (const float*)d_in[1];
    const float* Wup = (const float*)d_in[2];
    const float* bup = (const float*)d_in[3];
    const float* W1  = (const float*)d_in[4];
    const float* b1  = (const float*)d_in[5];
    const float* W2  = (const float*)d_in[6];
    const float* b2  = (const float*)d_in[7];
    float* P = (float*)d_out;

    bf16 *Phi, *Plo, *Xuh, *Xul, *Yth, *Ytl, *Xth, *Xtl, *W1h, *W1l, *W2h, *W2l, *Wuh, *Wul;
    float *part, *dinv;
    cudaGetSymbolAddress((void**)&Phi, g_Phi);  cudaGetSymbolAddress((void**)&Plo, g_Plo);
    cudaGetSymbolAddress((void**)&Xuh, g_Xuh);  cudaGetSymbolAddress((void**)&Xul, g_Xul);
    cudaGetSymbolAddress((void**)&Yth, g_Yth);  cudaGetSymbolAddress((void**)&Ytl, g_Ytl);
    cudaGetSymbolAddress((void**)&Xth, g_Xth);  cudaGetSymbolAddress((void**)&Xtl, g_Xtl);
    cudaGetSymbolAddress((void**)&W1h, g_W1h);  cudaGetSymbolAddress((void**)&W1l, g_W1l);
    cudaGetSymbolAddress((void**)&W2h, g_W2h);  cudaGetSymbolAddress((void**)&W2l, g_W2l);
    cudaGetSymbolAddress((void**)&Wuh, g_Wuh);  cudaGetSymbolAddress((void**)&Wul, g_Wul);
    cudaGetSymbolAddress((void**)&part, g_part);
    cudaGetSymbolAddress((void**)&dinv, g_dinv);

    cudaFuncSetAttribute(adj_mul_mma, cudaFuncAttributeMaxDynamicSharedMemorySize, ADJ_SMEM);
    cudaFuncSetAttribute(xxt_mma, cudaFuncAttributeMaxDynamicSharedMemorySize, XXT_SMEM);

    // ---- init: conversions ----
    cvt4<<<(NN * DD / 4 + 255) / 256, 256>>>(X, Xuh, Xul, NN * DD / 4);
    tcvt<<<dim3(DD / 32, NN / 32), dim3(32, 8)>>>(X, Xth, Xtl, NN, DD);
    cvt4<<<(NN * NN / 4 + 255) / 256, 256>>>(Wup, Wuh, Wul, NN * NN / 4);
    tcvt<<<dim3(4, 4), dim3(32, 8)>>>(W1, W1h, W1l, DD, DD);
    tcvt<<<dim3(4, 4), dim3(32, 8)>>>(W2, W2h, W2l, DD, DD);

    // new_nodes = Wup @ X (+ bup)
    adj_mul_mma<<<dim3(NN / 128, 2), 256, ADJ_SMEM>>>(Wuh, Wul, NN, Xth, Xtl, NN,
                                                      part, NN / 2, MM * DD);
    up_combine<<<NN * DD / 4 / 256, 256>>>(part, bup, Xuh, Xul);

    // initial block adjacency
    buildA<<<NN * NN / 4 / 256, 256>>>(A, Phi, Plo);
    xxt_mma<<<32 * 33 / 2, 256, XXT_SMEM>>>(Xuh + (size_t)NN * DD, Xul + (size_t)NN * DD,
                                            NN, Phi, Plo, nullptr, 0);

    for (int it = 0; it < 3; it++) {
        // conv1
        deg_hi<<<MM, 256>>>(Phi, dinv);
        adj_mul_mma<<<dim3(MM / 128, 1), 256, ADJ_SMEM>>>(Xuh, Xul, DD, W1h, W1l, DD,
                                                          part, DD, MM * DD);
        ytrans<<<dim3(MM / 32, DD / 32), dim3(32, 8)>>>(part, dinv, Yth, Ytl);
        adj_mul_mma<<<dim3(MM / 128, 2), 256, ADJ_SMEM>>>(Phi, Plo, MM, Yth, Ytl, MM,
                                                          part, MM / 2, MM * DD);
        xcombine<<<MM * DD / 4 / 256, 256>>>(part, dinv, b1, Xuh, Xul);
        // mid-loop adjacency rebuild
        xxt_mma<<<64 * 65 / 2, 256, XXT_SMEM>>>(Xuh, Xul, 0, Phi, Plo, nullptr, 0);
        // conv2
        deg_hi<<<MM, 256>>>(Phi, dinv);
        adj_mul_mma<<<dim3(MM / 128, 1), 256, ADJ_SMEM>>>(Xuh, Xul, DD, W2h, W2l, DD,
                                                          part, DD, MM * DD);
        ytrans<<<dim3(MM / 32, DD / 32), dim3(32, 8)>>>(part, dinv, Yth, Ytl);
        adj_mul_mma<<<dim3(MM / 128, 2), 256, ADJ_SMEM>>>(Phi, Plo, MM, Yth, Ytl, MM,
                                                          part, MM / 2, MM * DD);
        xcombine<<<MM * DD / 4 / 256, 256>>>(part, dinv, b2, Xuh, Xul);
    }

    // final A_out = sigmoid(Xu Xu^T) -> d_out (fp32)
    xxt_mma<<<64 * 65 / 2, 256, XXT_SMEM>>>(Xuh, Xul, 0, nullptr, nullptr, P, 1);

    (void)in_sizes; (void)n_in; (void)out_size;
}

// round 5
// speedup vs baseline: 6.1514x; 1.8306x over previous
#include <cuda_runtime.h>
#include <cuda_bf16.h>
#include <stdint.h>
#include <math.h>

#define NN 4096
#define MM 8192
#define DD 128

typedef __nv_bfloat16 bf16;

// ----------------- device scratch (no allocations allowed) -----------------
__device__ bf16  g_Phi[(size_t)MM * MM];
__device__ bf16  g_Xuh[MM * DD];
__device__ bf16  g_Xul[MM * DD];
__device__ bf16  g_Yth[DD * MM];
__device__ bf16  g_Xth[DD * NN];
__device__ bf16  g_Xtl[DD * NN];
__device__ bf16  g_W1h[DD * DD];
__device__ bf16  g_W1l[DD * DD];
__device__ bf16  g_W2h[DD * DD];
__device__ bf16  g_W2l[DD * DD];
__device__ bf16  g_Wuh[(size_t)NN * NN];
__device__ bf16  g_Wul[(size_t)NN * NN];
__device__ float g_part[4 * MM * DD];
__device__ float g_degp[64 * MM];
__device__ float g_dinv[MM];
__device__ float g_rsA[NN];

// ----------------------------- helpers ------------------------------------
__device__ __forceinline__ uint32_t s2u(const void* p) {
    uint32_t a;
    asm("{ .reg .u64 t; cvta.to.shared.u64 t, %1; cvt.u32.u64 %0, t; }"
        : "=r"(a) : "l"(p));
    return a;
}
#define SW128(o) ((o) ^ (((o) >> 3) & 0x70))

#define CPA(dst, src) asm volatile( \
    "cp.async.cg.shared.global [%0], [%1], 16;" :: "r"(dst), "l"(src))
#define CPCOMMIT() asm volatile("cp.async.commit_group;" ::: "memory")
#define CPWAIT(n)  asm volatile("cp.async.wait_group %0;" :: "n"(n) : "memory")

__device__ __forceinline__ void ldmx4(uint32_t* r, uint32_t a) {
    asm volatile("ldmatrix.sync.aligned.m8n8.x4.shared.b16 {%0,%1,%2,%3}, [%4];"
        : "=r"(r[0]), "=r"(r[1]), "=r"(r[2]), "=r"(r[3]) : "r"(a));
}
__device__ __forceinline__ void ldmx2(uint32_t* r, uint32_t a) {
    asm volatile("ldmatrix.sync.aligned.m8n8.x2.shared.b16 {%0,%1}, [%2];"
        : "=r"(r[0]), "=r"(r[1]) : "r"(a));
}
__device__ __forceinline__ void mma16816(float* c, const uint32_t* a, const uint32_t* b) {
    asm volatile(
        "mma.sync.aligned.m16n8k16.row.col.f32.bf16.bf16.f32 "
        "{%0,%1,%2,%3}, {%4,%5,%6,%7}, {%8,%9}, {%0,%1,%2,%3};"
        : "+f"(c[0]), "+f"(c[1]), "+f"(c[2]), "+f"(c[3])
        : "r"(a[0]), "r"(a[1]), "r"(a[2]), "r"(a[3]), "r"(b[0]), "r"(b[1]));
}

__device__ __forceinline__ uint32_t pk2(float a, float b, uint32_t& lo) {
    bf16 ha = __float2bfloat16(a), hb = __float2bfloat16(b);
    bf16 la = __float2bfloat16(a - __bfloat162float(ha));
    bf16 lb = __float2bfloat16(b - __bfloat162float(hb));
    lo = ((uint32_t)__bfloat16_as_ushort(lb) << 16) | __bfloat16_as_ushort(la);
    return ((uint32_t)__bfloat16_as_ushort(hb) << 16) | __bfloat16_as_ushort(ha);
}
__device__ __forceinline__ uint32_t pkh(float a, float b) {
    return (uint32_t)__bfloat16_as_ushort(__float2bfloat16(a)) |
           ((uint32_t)__bfloat16_as_ushort(__float2bfloat16(b)) << 16);
}
__device__ __forceinline__ float sigm(float x) {
    return __fdividef(1.0f, 1.0f + __expf(-x));
}

#define ADJ_SMEM 131072   // old 3-product kernel: 2 stages x 4 mats x 16KB
#define SGL_SMEM 65536    // single-product: 2 stages x 2 mats x 16KB
#define XXT_SMEM 131072   // 4 mats x 32KB; epilogue staging reuses it

// ===========================================================================
// adj_mul_mma (3-product hi/lo): part = A @ B^T. Used for the small GEMMs.
// ===========================================================================
__device__ __forceinline__ void adj_load(uint32_t sb, uint32_t stage,
    const bf16* Ah, const bf16* Al, int lda,
    const bf16* Bh, const bf16* Bl, int ldb, int m0, int k0, int tid)
{
    uint32_t base = sb + stage * 65536u;
#pragma unroll
    for (int p = 0; p < 16; p++) {
        int idx = tid + p * 256;
        int mat = idx >> 10, w = idx & 1023, r = w >> 3, cg = w & 7;
        const bf16* s;
        if      (mat == 0) s = Ah + (size_t)(m0 + r) * lda + k0 + cg * 8;
        else if (mat == 1) s = Al + (size_t)(m0 + r) * lda + k0 + cg * 8;
        else if (mat == 2) s = Bh + (size_t)r * ldb + k0 + cg * 8;
        else               s = Bl + (size_t)r * ldb + k0 + cg * 8;
        CPA(base + mat * 16384u + SW128(r * 128 + cg * 16), s);
    }
}

__global__ __launch_bounds__(256, 1) void adj_mul_mma(
    const bf16* __restrict__ Ah, const bf16* __restrict__ Al, int lda,
    const bf16* __restrict__ Bh, const bf16* __restrict__ Bl, int ldb,
    float* __restrict__ part, int kcta, int pstride)
{
    extern __shared__ char smem[];
    const uint32_t sb = s2u(smem);
    const int tid = threadIdx.x, wid = tid >> 5, lane = tid & 31;
    const int wm = wid & 1, wn = wid >> 1;
    const int m0 = blockIdx.x * 128;
    const int k0b = blockIdx.y * kcta;
    const int NT = kcta >> 6;

    float acc[4][4][4];
#pragma unroll
    for (int i = 0; i < 4; i++)
#pragma unroll
        for (int j = 0; j < 4; j++)
#pragma unroll
            for (int e = 0; e < 4; e++) acc[i][j][e] = 0.0f;

    const uint32_t swz = (uint32_t)(lane & 7) << 4;
    uint32_t arow[4], brow[4];
#pragma unroll
    for (int t = 0; t < 4; t++) {
        arow[t] = (uint32_t)((wm * 64 + t * 16 + (lane & 15)) * 128);
        brow[t] = (uint32_t)((wn * 32 + t * 8 + (lane & 7)) * 128);
    }
    const uint32_t akh = (uint32_t)((lane >> 4) * 16);
    const uint32_t bkh = (uint32_t)(((lane >> 3) & 1) * 16);

    adj_load(sb, 0, Ah, Al, lda, Bh, Bl, ldb, m0, k0b, tid);
    CPCOMMIT();

    for (int kt = 0; kt < NT; kt++) {
        if (kt + 1 < NT) {
            adj_load(sb, (kt + 1) & 1, Ah, Al, lda, Bh, Bl, ldb,
                     m0, k0b + (kt + 1) * 64, tid);
            CPCOMMIT();
            CPWAIT(1);
        } else {
            CPWAIT(0);
        }
        __syncthreads();

        uint32_t st = sb + (uint32_t)(kt & 1) * 65536u;
#pragma unroll
        for (int ks = 0; ks < 4; ks++) {
            uint32_t axk = ((uint32_t)(ks * 32) + akh) ^ swz;
            uint32_t bxk = ((uint32_t)(ks * 32) + bkh) ^ swz;
            uint32_t ah[4][4], al[4][4], bh[4][2], bl[4][2];
#pragma unroll
            for (int t = 0; t < 4; t++) {
                ldmx4(ah[t], st + arow[t] + axk);
                ldmx4(al[t], st + 16384u + arow[t] + axk);
                ldmx2(bh[t], st + 32768u + brow[t] + bxk);
                ldmx2(bl[t], st + 49152u + brow[t] + bxk);
            }
#pragma unroll
            for (int tm = 0; tm < 4; tm++)
#pragma unroll
                for (int tn = 0; tn < 4; tn++) {
                    mma16816(acc[tm][tn], ah[tm], bh[tn]);
                    mma16816(acc[tm][tn], al[tm], bh[tn]);
                    mma16816(acc[tm][tn], ah[tm], bl[tn]);
                }
        }
        __syncthreads();
    }

    float* dst = part + (size_t)blockIdx.y * pstride + (size_t)m0 * 128;
#pragma unroll
    for (int tm = 0; tm < 4; tm++)
#pragma unroll
        for (int tn = 0; tn < 4; tn++) {
            int r0 = wm * 64 + tm * 16 + (lane >> 2);
            int c0 = wn * 32 + tn * 8 + 2 * (lane & 3);
            *(float2*)(dst + (size_t)r0 * 128 + c0) =
                make_float2(acc[tm][tn][0], acc[tm][tn][1]);
            *(float2*)(dst + (size_t)(r0 + 8) * 128 + c0) =
                make_float2(acc[tm][tn][2], acc[tm][tn][3]);
        }
}

// ===========================================================================
// adj_single (single-product bf16): part = A @ B^T for the big P@Y GEMM.
// 64KB smem -> 2 CTAs/SM; grid(M/128, ksplit=4).
// ===========================================================================
__device__ __forceinline__ void sgl_load(uint32_t sb, uint32_t stage,
    const bf16* Ah, int lda, const bf16* Bh, int ldb, int m0, int k0, int tid)
{
    uint32_t base = sb + stage * 32768u;
#pragma unroll
    for (int p = 0; p < 8; p++) {
        int idx = tid + p * 256;
        int mat = idx >> 10, w = idx & 1023, r = w >> 3, cg = w & 7;
        const bf16* s = mat ? (Bh + (size_t)r * ldb + k0 + cg * 8)
                            : (Ah + (size_t)(m0 + r) * lda + k0 + cg * 8);
        CPA(base + mat * 16384u + SW128(r * 128 + cg * 16), s);
    }
}

__global__ __launch_bounds__(256, 2) void adj_single(
    const bf16* __restrict__ Ah, int lda,
    const bf16* __restrict__ Bh, int ldb,
    float* __restrict__ part, int kcta, int pstride)
{
    extern __shared__ char smem[];
    const uint32_t sb = s2u(smem);
    const int tid = threadIdx.x, wid = tid >> 5, lane = tid & 31;
    const int wm = wid & 1, wn = wid >> 1;
    const int m0 = blockIdx.x * 128;
    const int k0b = blockIdx.y * kcta;
    const int NT = kcta >> 6;

    float acc[4][4][4];
#pragma unroll
    for (int i = 0; i < 4; i++)
#pragma unroll
        for (int j = 0; j < 4; j++)
#pragma unroll
            for (int e = 0; e < 4; e++) acc[i][j][e] = 0.0f;

    const uint32_t swz = (uint32_t)(lane & 7) << 4;
    uint32_t arow[4], brow[4];
#pragma unroll
    for (int t = 0; t < 4; t++) {
        arow[t] = (uint32_t)((wm * 64 + t * 16 + (lane & 15)) * 128);
        brow[t] = (uint32_t)((wn * 32 + t * 8 + (lane & 7)) * 128);
    }
    const uint32_t akh = (uint32_t)((lane >> 4) * 16);
    const uint32_t bkh = (uint32_t)(((lane >> 3) & 1) * 16);

    sgl_load(sb, 0, Ah, lda, Bh, ldb, m0, k0b, tid);
    CPCOMMIT();

    for (int kt = 0; kt < NT; kt++) {
        if (kt + 1 < NT) {
            sgl_load(sb, (kt + 1) & 1, Ah, lda, Bh, ldb, m0, k0b + (kt + 1) * 64, tid);
            CPCOMMIT();
            CPWAIT(1);
        } else {
            CPWAIT(0);
        }
        __syncthreads();

        uint32_t st = sb + (uint32_t)(kt & 1) * 32768u;
#pragma unroll
        for (int ks = 0; ks < 4; ks++) {
            uint32_t axk = ((uint32_t)(ks * 32) + akh) ^ swz;
            uint32_t bxk = ((uint32_t)(ks * 32) + bkh) ^ swz;
            uint32_t ah[4][4], bh[4][2];
#pragma unroll
            for (int t = 0; t < 4; t++) {
                ldmx4(ah[t], st + arow[t] + axk);
                ldmx2(bh[t], st + 16384u + brow[t] + bxk);
            }
#pragma unroll
            for (int tm = 0; tm < 4; tm++)
#pragma unroll
                for (int tn = 0; tn < 4; tn++)
                    mma16816(acc[tm][tn], ah[tm], bh[tn]);
        }
        __syncthreads();
    }

    float* dst = part + (size_t)blockIdx.y * pstride + (size_t)m0 * 128;
#pragma unroll
    for (int tm = 0; tm < 4; tm++)
#pragma unroll
        for (int tn = 0; tn < 4; tn++) {
            int r0 = wm * 64 + tm * 16 + (lane >> 2);
            int c0 = wn * 32 + tn * 8 + 2 * (lane & 3);
            *(float2*)(dst + (size_t)r0 * 128 + c0) =
                make_float2(acc[tm][tn][0], acc[tm][tn][1]);
            *(float2*)(dst + (size_t)(r0 + 8) * 128 + c0) =
                make_float2(acc[tm][tn][2], acc[tm][tn][3]);
        }
}

// ===========================================================================
// xxt_mma: sigmoid(X X^T), X hi/lo [n x 128], upper-tri 128x128 tile pairs.
// mode 0: bf16 into Ph (+mirror) + deterministic deg partials degp[bj][row].
// mode 1: fp32 into Pf (+mirror), no deg.
// ===========================================================================
__global__ __launch_bounds__(256, 1) void xxt_mma(
    const bf16* __restrict__ Xh, const bf16* __restrict__ Xl, int ooff,
    bf16* __restrict__ Ph, float* __restrict__ Pf,
    float* __restrict__ degp, int mode)
{
    extern __shared__ char smem[];
    const uint32_t sb = s2u(smem);
    const int tid = threadIdx.x, wid = tid >> 5, lane = tid & 31;
    const int wm = wid & 1, wn = wid >> 1;

    int b = blockIdx.x;
    int bj = (int)((sqrtf(8.0f * (float)b + 1.0f) - 1.0f) * 0.5f);
    while ((bj + 1) * (bj + 2) / 2 <= b) bj++;
    while (bj * (bj + 1) / 2 > b) bj--;
    int bi = b - bj * (bj + 1) / 2;

#pragma unroll
    for (int p = 0; p < 32; p++) {
        int idx = tid + p * 256;
        int mat = idx >> 11, w = idx & 2047, kb = w >> 10, ww = w & 1023;
        int r = ww >> 3, cg = ww & 7;
        const bf16* base = (mat & 1) ? Xl : Xh;
        int rb = ((mat < 2) ? bi : bj) * 128;
        CPA(sb + (uint32_t)mat * 32768u + (uint32_t)kb * 16384u +
                SW128(r * 128 + cg * 16),
            base + (size_t)(rb + r) * 128 + kb * 64 + cg * 8);
    }
    CPCOMMIT();

    float acc[4][4][4];
#pragma unroll
    for (int i = 0; i < 4; i++)
#pragma unroll
        for (int j = 0; j < 4; j++)
#pragma unroll
            for (int e = 0; e < 4; e++) acc[i][j][e] = 0.0f;

    const uint32_t swz = (uint32_t)(lane & 7) << 4;
    uint32_t arow[4], brow[4];
#pragma unroll
    for (int t = 0; t < 4; t++) {
        arow[t] = (uint32_t)((wm * 64 + t * 16 + (lane & 15)) * 128);
        brow[t] = (uint32_t)((wn * 32 + t * 8 + (lane & 7)) * 128);
    }
    const uint32_t akh = (uint32_t)((lane >> 4) * 16);
    const uint32_t bkh = (uint32_t)(((lane >> 3) & 1) * 16);

    CPWAIT(0);
    __syncthreads();

#pragma unroll
    for (int ks = 0; ks < 8; ks++) {
        uint32_t kbo = (uint32_t)(ks >> 2) * 16384u;
        uint32_t axk = ((uint32_t)((ks & 3) * 32) + akh) ^ swz;
        uint32_t bxk = ((uint32_t)((ks & 3) * 32) + bkh) ^ swz;
        uint32_t ah[4][4], al[4][4], bh[4][2], bl[4][2];
#pragma unroll
        for (int t = 0; t < 4; t++) {
            ldmx4(ah[t], sb + kbo + arow[t] + axk);
            ldmx4(al[t], sb + 32768u + kbo + arow[t] + axk);
            ldmx2(bh[t], sb + 65536u + kbo + brow[t] + bxk);
            ldmx2(bl[t], sb + 98304u + kbo + brow[t] + bxk);
        }
#pragma unroll
        for (int tm = 0; tm < 4; tm++)
#pragma unroll
            for (int tn = 0; tn < 4; tn++) {
                mma16816(acc[tm][tn], ah[tm], bh[tn]);
                mma16816(acc[tm][tn], al[tm], bh[tn]);
                mma16816(acc[tm][tn], ah[tm], bl[tn]);
            }
    }
    __syncthreads();   // tiles consumed; smem reused for fp32 staging

    const int gi0 = ooff + bi * 128;
    const int gj0 = ooff + bj * 128;
    float* sf = (float*)smem;   // [128][132] fp32 sigmoid staging

#pragma unroll
    for (int tm = 0; tm < 4; tm++)
#pragma unroll
        for (int tn = 0; tn < 4; tn++) {
            int r0 = wm * 64 + tm * 16 + (lane >> 2);
            int c0 = wn * 32 + tn * 8 + 2 * (lane & 3);
            sf[r0 * 132 + c0]           = sigm(acc[tm][tn][0]);
            sf[r0 * 132 + c0 + 1]       = sigm(acc[tm][tn][1]);
            sf[(r0 + 8) * 132 + c0]     = sigm(acc[tm][tn][2]);
            sf[(r0 + 8) * 132 + c0 + 1] = sigm(acc[tm][tn][3]);
        }
    __syncthreads();

    const int r = tid >> 1;
    const int cb0 = (tid & 1) * 64;

    if (mode == 0) {
        float s = 0.0f;
#pragma unroll
        for (int c8 = 0; c8 < 8; c8++) {
            float v[8];
#pragma unroll
            for (int e = 0; e < 8; e++) {
                v[e] = sf[r * 132 + cb0 + c8 * 8 + e];
                s += v[e];
            }
            uint4 hv;
            hv.x = pkh(v[0], v[1]); hv.y = pkh(v[2], v[3]);
            hv.z = pkh(v[4], v[5]); hv.w = pkh(v[6], v[7]);
            *(uint4*)(Ph + (size_t)(gi0 + r) * MM + gj0 + cb0 + c8 * 8) = hv;
        }
        float full = s + __shfl_xor_sync(0xffffffffu, s, 1);
        if (!(tid & 1)) degp[(size_t)bj * MM + gi0 + r] = full;

        if (bi != bj) {
            float s2 = 0.0f;
#pragma unroll
            for (int c8 = 0; c8 < 8; c8++) {
                float v[8];
#pragma unroll
                for (int e = 0; e < 8; e++) {
                    v[e] = sf[(cb0 + c8 * 8 + e) * 132 + r];
                    s2 += v[e];
                }
                uint4 hv;
                hv.x = pkh(v[0], v[1]); hv.y = pkh(v[2], v[3]);
                hv.z = pkh(v[4], v[5]); hv.w = pkh(v[6], v[7]);
                *(uint4*)(Ph + (size_t)(gj0 + r) * MM + gi0 + cb0 + c8 * 8) = hv;
            }
            float full2 = s2 + __shfl_xor_sync(0xffffffffu, s2, 1);
            if (!(tid & 1)) degp[(size_t)bi * MM + gj0 + r] = full2;
        }
    } else {
#pragma unroll
        for (int c4 = 0; c4 < 16; c4++) {
            int cb = cb0 + c4 * 4;
            float4 o = make_float4(sf[r * 132 + cb], sf[r * 132 + cb + 1],
                                   sf[r * 132 + cb + 2], sf[r * 132 + cb + 3]);
            *(float4*)(Pf + (size_t)(gi0 + r) * MM + gj0 + cb) = o;
        }
        if (bi != bj) {
#pragma unroll
            for (int c4 = 0; c4 < 16; c4++) {
                int cb = cb0 + c4 * 4;
                float4 o = make_float4(sf[(cb + 0) * 132 + r], sf[(cb + 1) * 132 + r],
                                       sf[(cb + 2) * 132 + r], sf[(cb + 3) * 132 + r]);
                *(float4*)(Pf + (size_t)(gj0 + r) * MM + gi0 + cb) = o;
            }
        }
    }
}

// ------------------------ small elementwise kernels ------------------------
__global__ __launch_bounds__(256) void cvt4(const float* __restrict__ s,
                                            bf16* __restrict__ dh, bf16* __restrict__ dl, int n4)
{
    int i = blockIdx.x * 256 + threadIdx.x;
    if (i >= n4) return;
    float4 v = ((const float4*)s)[i];
    uint2 h, l;
    h.x = pk2(v.x, v.y, l.x);
    h.y = pk2(v.z, v.w, l.y);
    ((uint2*)dh)[i] = h;
    ((uint2*)dl)[i] = l;
}

__global__ void tcvt(const float* __restrict__ src, bf16* __restrict__ dh,
                     bf16* __restrict__ dl, int R, int C)
{
    __shared__ float t[32][33];
    int c0 = blockIdx.x * 32, r0 = blockIdx.y * 32;
    for (int i = threadIdx.y; i < 32; i += 8)
        t[i][threadIdx.x] = src[(size_t)(r0 + i) * C + c0 + threadIdx.x];
    __syncthreads();
    for (int i = threadIdx.y; i < 32; i += 8) {
        float v = t[threadIdx.x][i];
        bf16 h = __float2bfloat16(v);
        dh[(size_t)(c0 + i) * R + r0 + threadIdx.x] = h;
        dl[(size_t)(c0 + i) * R + r0 + threadIdx.x] =
            __float2bfloat16(v - __bfloat162float(h));
    }
}

// Yt[c][j] = dinv[j] * part[j][c]  (hi only)
__global__ void ytrans(const float* __restrict__ part, const float* __restrict__ dinv,
                       bf16* __restrict__ yh)
{
    __shared__ float t[32][33];
    int j0 = blockIdx.x * 32, c0 = blockIdx.y * 32;
    for (int i = threadIdx.y; i < 32; i += 8)
        t[i][threadIdx.x] = part[(size_t)(j0 + i) * 128 + c0 + threadIdx.x] * dinv[j0 + i];
    __syncthreads();
    for (int i = threadIdx.y; i < 32; i += 8)
        yh[(size_t)(c0 + i) * MM + j0 + threadIdx.x] = __float2bfloat16(t[threadIdx.x][i]);
}

// Xu = relu(dinv[i]*(sum of 4 partials) + bias[c]) -> hi/lo
__global__ __launch_bounds__(256) void xcombine4(const float* __restrict__ part,
    const float* __restrict__ dinv, const float* __restrict__ bias,
    bf16* __restrict__ xh, bf16* __restrict__ xl)
{
    int idx = blockIdx.x * 256 + threadIdx.x;
    int base = idx * 4, row = base >> 7, c = base & 127;
    float4 a = ((const float4*)part)[idx];
    float4 b = ((const float4*)(part + (size_t)MM * DD))[idx];
    float4 d = ((const float4*)(part + (size_t)2 * MM * DD))[idx];
    float4 e = ((const float4*)(part + (size_t)3 * MM * DD))[idx];
    float di = dinv[row];
    float v0 = fmaxf(di * (a.x + b.x + d.x + e.x) + bias[c + 0], 0.0f);
    float v1 = fmaxf(di * (a.y + b.y + d.y + e.y) + bias[c + 1], 0.0f);
    float v2 = fmaxf(di * (a.z + b.z + d.z + e.z) + bias[c + 2], 0.0f);
    float v3 = fmaxf(di * (a.w + b.w + d.w + e.w) + bias[c + 3], 0.0f);
    uint2 h, l;
    h.x = pk2(v0, v1, l.x);
    h.y = pk2(v2, v3, l.y);
    ((uint2*)xh)[idx] = h;
    ((uint2*)xl)[idx] = l;
}

__global__ __launch_bounds__(256) void up_combine(const float* __restrict__ part,
    const float* __restrict__ bup, bf16* __restrict__ xh, bf16* __restrict__ xl)
{
    int idx = blockIdx.x * 256 + threadIdx.x;
    int base = idx * 4, row = base >> 7;
    float4 a = ((const float4*)part)[idx];
    float4 b = ((const float4*)(part + (size_t)MM * DD))[idx];
    float bu = bup[row];
    uint2 h, l;
    h.x = pk2(a.x + b.x + bu, a.y + b.y + bu, l.x);
    h.y = pk2(a.z + b.z + bu, a.w + b.w + bu, l.y);
    ((uint2*)(xh + (size_t)NN * DD))[idx] = h;
    ((uint2*)(xl + (size_t)NN * DD))[idx] = l;
}

// A (fp32) -> bf16 into 3 quadrants of Phi
__global__ __launch_bounds__(256) void buildA(const float* __restrict__ A,
                                              bf16* __restrict__ Ph)
{
    int idx = blockIdx.x * 256 + threadIdx.x;
    int i = idx >> 10, j4 = idx & 1023;
    float4 v = ((const float4*)A)[(size_t)i * 1024 + j4];
    uint2 h;
    h.x = pkh(v.x, v.y);
    h.y = pkh(v.z, v.w);
    size_t o0 = (size_t)i * MM + j4 * 4;
    *(uint2*)(Ph + o0) = h;
    *(uint2*)(Ph + o0 + NN) = h;
    *(uint2*)(Ph + (size_t)(i + NN) * MM + j4 * 4) = h;
}

// fp32 row sums of A (deterministic tree reduce)
__global__ __launch_bounds__(256) void rsA_kernel(const float* __restrict__ A,
                                                  float* __restrict__ rsA)
{
    __shared__ float red[256];
    const float4* p = (const float4*)(A + (size_t)blockIdx.x * NN);
    float s = 0.0f;
    for (int j = threadIdx.x; j < NN / 4; j += 256) {
        float4 v = p[j];
        s += (v.x + v.y) + (v.z + v.w);
    }
    red[threadIdx.x] = s;
    __syncthreads();
    for (int st = 128; st > 0; st >>= 1) {
        if (threadIdx.x < st) red[threadIdx.x] += red[threadIdx.x + st];
        __syncthreads();
    }
    if (threadIdx.x == 0) rsA[blockIdx.x] = red[0];
}

// init deg: rows<N: 2*rowsum(A); rows>=N: rowsum(A) + sum of 32 S-partials
__global__ __launch_bounds__(256) void deg_init(const float* __restrict__ rsA,
    const float* __restrict__ degp, float* __restrict__ dinv)
{
    int i = blockIdx.x * 256 + threadIdx.x;
    float d;
    if (i < NN) {
        d = 2.0f * rsA[i];
    } else {
        d = rsA[i - NN];
#pragma unroll
        for (int s = 0; s < 32; s++) d += degp[(size_t)s * MM + i];
    }
    dinv[i] = d > 0.0f ? rsqrtf(d) : 0.0f;
}

__global__ __launch_bounds__(256) void deg_reduce(const float* __restrict__ degp,
                                                  float* __restrict__ dinv)
{
    int i = blockIdx.x * 256 + threadIdx.x;
    float d = 0.0f;
#pragma unroll
    for (int s = 0; s < 64; s++) d += degp[(size_t)s * MM + i];
    dinv[i] = d > 0.0f ? rsqrtf(d) : 0.0f;
}

// ---------------------------------------------------------------------------
extern "C" void kernel_launch(void* const* d_in, const int* in_sizes, int n_in,
                              void* d_out, int out_size)
{
    const float* X   = (const float*)d_in[0];
    const float* A   = (const float*)d_in[1];
    const float* Wup = (const float*)d_in[2];
    const float* bup = (const float*)d_in[3];
    const float* W1  = (const float*)d_in[4];
    const float* b1  = (const float*)d_in[5];
    const float* W2  = (const float*)d_in[6];
    const float* b2  = (const float*)d_in[7];
    float* P = (float*)d_out;

    bf16 *Phi, *Xuh, *Xul, *Yth, *Xth, *Xtl, *W1h, *W1l, *W2h, *W2l, *Wuh, *Wul;
    float *part, *degp, *dinv, *rsA;
    cudaGetSymbolAddress((void**)&Phi, g_Phi);
    cudaGetSymbolAddress((void**)&Xuh, g_Xuh);  cudaGetSymbolAddress((void**)&Xul, g_Xul);
    cudaGetSymbolAddress((void**)&Yth, g_Yth);
    cudaGetSymbolAddress((void**)&Xth, g_Xth);  cudaGetSymbolAddress((void**)&Xtl, g_Xtl);
    cudaGetSymbolAddress((void**)&W1h, g_W1h);  cudaGetSymbolAddress((void**)&W1l, g_W1l);
    cudaGetSymbolAddress((void**)&W2h, g_W2h);  cudaGetSymbolAddress((void**)&W2l, g_W2l);
    cudaGetSymbolAddress((void**)&Wuh, g_Wuh);  cudaGetSymbolAddress((void**)&Wul, g_Wul);
    cudaGetSymbolAddress((void**)&part, g_part);
    cudaGetSymbolAddress((void**)&degp, g_degp);
    cudaGetSymbolAddress((void**)&dinv, g_dinv);
    cudaGetSymbolAddress((void**)&rsA, g_rsA);

    cudaFuncSetAttribute(adj_mul_mma, cudaFuncAttributeMaxDynamicSharedMemorySize, ADJ_SMEM);
    cudaFuncSetAttribute(adj_single, cudaFuncAttributeMaxDynamicSharedMemorySize, SGL_SMEM);
    cudaFuncSetAttribute(xxt_mma, cudaFuncAttributeMaxDynamicSharedMemorySize, XXT_SMEM);

    // ---- init conversions ----
    cvt4<<<(NN * DD / 4 + 255) / 256, 256>>>(X, Xuh, Xul, NN * DD / 4);
    tcvt<<<dim3(DD / 32, NN / 32), dim3(32, 8)>>>(X, Xth, Xtl, NN, DD);
    cvt4<<<(NN * NN / 4 + 255) / 256, 256>>>(Wup, Wuh, Wul, NN * NN / 4);
    tcvt<<<dim3(4, 4), dim3(32, 8)>>>(W1, W1h, W1l, DD, DD);
    tcvt<<<dim3(4, 4), dim3(32, 8)>>>(W2, W2h, W2l, DD, DD);

    // new_nodes = Wup @ X (+ bup)
    adj_mul_mma<<<dim3(NN / 128, 2), 256, ADJ_SMEM>>>(Wuh, Wul, NN, Xth, Xtl, NN,
                                                      part, NN / 2, MM * DD);
    up_combine<<<NN * DD / 4 / 256, 256>>>(part, bup, Xuh, Xul);

    // initial block adjacency (bf16) + fused S row-sum partials
    buildA<<<NN * NN / 4 / 256, 256>>>(A, Phi);
    rsA_kernel<<<NN, 256>>>(A, rsA);
    xxt_mma<<<32 * 33 / 2, 256, XXT_SMEM>>>(Xuh + (size_t)NN * DD, Xul + (size_t)NN * DD,
                                            NN, Phi, nullptr, degp, 0);
    deg_init<<<MM / 256, 256>>>(rsA, degp, dinv);

    for (int it = 0; it < 3; it++) {
        // conv1 (dinv from previous rebuild / init)
        adj_mul_mma<<<dim3(MM / 128, 1), 256, ADJ_SMEM>>>(Xuh, Xul, DD, W1h, W1l, DD,
                                                          part, DD, MM * DD);
        ytrans<<<dim3(MM / 32, DD / 32), dim3(32, 8)>>>(part, dinv, Yth);
        adj_single<<<dim3(MM / 128, 4), 256, SGL_SMEM>>>(Phi, MM, Yth, MM,
                                                         part, MM / 4, MM * DD);
        xcombine4<<<MM * DD / 4 / 256, 256>>>(part, dinv, b1, Xuh, Xul);
        // mid-loop adjacency rebuild + fused deg partials
        xxt_mma<<<64 * 65 / 2, 256, XXT_SMEM>>>(Xuh, Xul, 0, Phi, nullptr, degp, 0);
        deg_reduce<<<MM / 256, 256>>>(degp, dinv);
        // conv2
        adj_mul_mma<<<dim3(MM / 128, 1), 256, ADJ_SMEM>>>(Xuh, Xul, DD, W2h, W2l, DD,
                                                          part, DD, MM * DD);
        ytrans<<<dim3(MM / 32, DD / 32), dim3(32, 8)>>>(part, dinv, Yth);
        adj_single<<<dim3(MM / 128, 4), 256, SGL_SMEM>>>(Phi, MM, Yth, MM,
                                                         part, MM / 4, MM * DD);
        xcombine4<<<MM * DD / 4 / 256, 256>>>(part, dinv, b2, Xuh, Xul);
    }

    // final A_out = sigmoid(Xu Xu^T) -> d_out (fp32)
    xxt_mma<<<64 * 65 / 2, 256, XXT_SMEM>>>(Xuh, Xul, 0, nullptr, P, nullptr, 1);

    (void)in_sizes; (void)n_in; (void)out_size;
}

// round 6
// speedup vs baseline: 7.8933x; 1.2832x over previous
#include <cuda_runtime.h>
#include <cuda_bf16.h>
#include <stdint.h>
#include <math.h>

#define NN 4096
#define MM 8192
#define DD 128

typedef __nv_bfloat16 bf16;

// ----------------- device scratch (no allocations allowed) -----------------
__device__ bf16  g_Phi[(size_t)MM * MM];
__device__ bf16  g_Xuh[MM * DD];
__device__ bf16  g_Yth[DD * MM];
__device__ bf16  g_Xth[DD * NN];
__device__ bf16  g_W1h[DD * DD];
__device__ bf16  g_W2h[DD * DD];
__device__ bf16  g_Wuh[(size_t)NN * NN];
__device__ float g_part[4 * MM * DD];
__device__ float g_degp[64 * MM];
__device__ float g_dinv[MM];
__device__ float g_rsA[NN];

// ----------------------------- helpers ------------------------------------
__device__ __forceinline__ uint32_t s2u(const void* p) {
    uint32_t a;
    asm("{ .reg .u64 t; cvta.to.shared.u64 t, %1; cvt.u32.u64 %0, t; }"
        : "=r"(a) : "l"(p));
    return a;
}
#define SW128(o) ((o) ^ (((o) >> 3) & 0x70))

#define CPA(dst, src) asm volatile( \
    "cp.async.cg.shared.global [%0], [%1], 16;" :: "r"(dst), "l"(src))
#define CPCOMMIT() asm volatile("cp.async.commit_group;" ::: "memory")
#define CPWAIT(n)  asm volatile("cp.async.wait_group %0;" :: "n"(n) : "memory")

__device__ __forceinline__ void ldmx4(uint32_t* r, uint32_t a) {
    asm volatile("ldmatrix.sync.aligned.m8n8.x4.shared.b16 {%0,%1,%2,%3}, [%4];"
        : "=r"(r[0]), "=r"(r[1]), "=r"(r[2]), "=r"(r[3]) : "r"(a));
}
__device__ __forceinline__ void ldmx2(uint32_t* r, uint32_t a) {
    asm volatile("ldmatrix.sync.aligned.m8n8.x2.shared.b16 {%0,%1}, [%2];"
        : "=r"(r[0]), "=r"(r[1]) : "r"(a));
}
__device__ __forceinline__ void mma16816(float* c, const uint32_t* a, const uint32_t* b) {
    asm volatile(
        "mma.sync.aligned.m16n8k16.row.col.f32.bf16.bf16.f32 "
        "{%0,%1,%2,%3}, {%4,%5,%6,%7}, {%8,%9}, {%0,%1,%2,%3};"
        : "+f"(c[0]), "+f"(c[1]), "+f"(c[2]), "+f"(c[3])
        : "r"(a[0]), "r"(a[1]), "r"(a[2]), "r"(a[3]), "r"(b[0]), "r"(b[1]));
}

__device__ __forceinline__ uint32_t pkh(float a, float b) {
    return (uint32_t)__bfloat16_as_ushort(__float2bfloat16(a)) |
           ((uint32_t)__bfloat16_as_ushort(__float2bfloat16(b)) << 16);
}
__device__ __forceinline__ float sigm(float x) {
    return __fdividef(1.0f, 1.0f + __expf(-x));
}

#define SGL_SMEM 65536                       // 2 stages x 2 mats x 16KB
#define XXT_SMEM (65536 + 128 * 69 * 4)      // 2 tiles 32KB + staging [128][69] f32

// ===========================================================================
// adj_single: part = A @ B^T (bf16 single product). A [M x K] row-major lda,
// B [128 x K] row-major ldb. grid(x = M/128, y = ksplit).
// ===========================================================================
__device__ __forceinline__ void sgl_load(uint32_t sb, uint32_t stage,
    const bf16* Ah, int lda, const bf16* Bh, int ldb, int m0, int k0, int tid)
{
    uint32_t base = sb + stage * 32768u;
#pragma unroll
    for (int p = 0; p < 8; p++) {
        int idx = tid + p * 256;
        int mat = idx >> 10, w = idx & 1023, r = w >> 3, cg = w & 7;
        const bf16* s = mat ? (Bh + (size_t)r * ldb + k0 + cg * 8)
                            : (Ah + (size_t)(m0 + r) * lda + k0 + cg * 8);
        CPA(base + mat * 16384u + SW128(r * 128 + cg * 16), s);
    }
}

__global__ __launch_bounds__(256, 2) void adj_single(
    const bf16* __restrict__ Ah, int lda,
    const bf16* __restrict__ Bh, int ldb,
    float* __restrict__ part, int kcta, int pstride)
{
    extern __shared__ char smem[];
    const uint32_t sb = s2u(smem);
    const int tid = threadIdx.x, wid = tid >> 5, lane = tid & 31;
    const int wm = wid & 1, wn = wid >> 1;
    const int m0 = blockIdx.x * 128;
    const int k0b = blockIdx.y * kcta;
    const int NT = kcta >> 6;

    float acc[4][4][4];
#pragma unroll
    for (int i = 0; i < 4; i++)
#pragma unroll
        for (int j = 0; j < 4; j++)
#pragma unroll
            for (int e = 0; e < 4; e++) acc[i][j][e] = 0.0f;

    const uint32_t swz = (uint32_t)(lane & 7) << 4;
    uint32_t arow[4], brow[4];
#pragma unroll
    for (int t = 0; t < 4; t++) {
        arow[t] = (uint32_t)((wm * 64 + t * 16 + (lane & 15)) * 128);
        brow[t] = (uint32_t)((wn * 32 + t * 8 + (lane & 7)) * 128);
    }
    const uint32_t akh = (uint32_t)((lane >> 4) * 16);
    const uint32_t bkh = (uint32_t)(((lane >> 3) & 1) * 16);

    sgl_load(sb, 0, Ah, lda, Bh, ldb, m0, k0b, tid);
    CPCOMMIT();

    for (int kt = 0; kt < NT; kt++) {
        if (kt + 1 < NT) {
            sgl_load(sb, (kt + 1) & 1, Ah, lda, Bh, ldb, m0, k0b + (kt + 1) * 64, tid);
            CPCOMMIT();
            CPWAIT(1);
        } else {
            CPWAIT(0);
        }
        __syncthreads();

        uint32_t st = sb + (uint32_t)(kt & 1) * 32768u;
#pragma unroll
        for (int ks = 0; ks < 4; ks++) {
            uint32_t axk = ((uint32_t)(ks * 32) + akh) ^ swz;
            uint32_t bxk = ((uint32_t)(ks * 32) + bkh) ^ swz;
            uint32_t ah[4][4], bh[4][2];
#pragma unroll
            for (int t = 0; t < 4; t++) {
                ldmx4(ah[t], st + arow[t] + axk);
                ldmx2(bh[t], st + 16384u + brow[t] + bxk);
            }
#pragma unroll
            for (int tm = 0; tm < 4; tm++)
#pragma unroll
                for (int tn = 0; tn < 4; tn++)
                    mma16816(acc[tm][tn], ah[tm], bh[tn]);
        }
        __syncthreads();
    }

    float* dst = part + (size_t)blockIdx.y * pstride + (size_t)m0 * 128;
#pragma unroll
    for (int tm = 0; tm < 4; tm++)
#pragma unroll
        for (int tn = 0; tn < 4; tn++) {
            int r0 = wm * 64 + tm * 16 + (lane >> 2);
            int c0 = wn * 32 + tn * 8 + 2 * (lane & 3);
            *(float2*)(dst + (size_t)r0 * 128 + c0) =
                make_float2(acc[tm][tn][0], acc[tm][tn][1]);
            *(float2*)(dst + (size_t)(r0 + 8) * 128 + c0) =
                make_float2(acc[tm][tn][2], acc[tm][tn][3]);
        }
}

// ===========================================================================
// xxt_single: sigmoid(X X^T), X bf16 [n x 128], upper-tri 128x128 tile pairs,
// single bf16 product. mode 0: bf16 into Ph (+mirror) + deterministic deg
// partials degp[tile][row]. mode 1: fp32 into Pf (+mirror).
// Epilogue staged in two 64-column passes through sf[128][69].
// ===========================================================================
__global__ __launch_bounds__(256, 2) void xxt_single(
    const bf16* __restrict__ Xh, int ooff,
    bf16* __restrict__ Ph, float* __restrict__ Pf,
    float* __restrict__ degp, int mode)
{
    extern __shared__ char smem[];
    const uint32_t sb = s2u(smem);
    const int tid = threadIdx.x, wid = tid >> 5, lane = tid & 31;
    const int wm = wid & 1, wn = wid >> 1;

    int b = blockIdx.x;
    int bj = (int)((sqrtf(8.0f * (float)b + 1.0f) - 1.0f) * 0.5f);
    while ((bj + 1) * (bj + 2) / 2 <= b) bj++;
    while (bj * (bj + 1) / 2 > b) bj--;
    int bi = b - bj * (bj + 1) / 2;

    // load Ih (rows of bi), Jh (rows of bj): each [128x128] bf16, 2 SW128 chunks
#pragma unroll
    for (int p = 0; p < 16; p++) {
        int idx = tid + p * 256;
        int mat = idx >> 11, w = idx & 2047, kb = w >> 10, ww = w & 1023;
        int r = ww >> 3, cg = ww & 7;
        int rb = (mat ? bj : bi) * 128;
        CPA(sb + (uint32_t)mat * 32768u + (uint32_t)kb * 16384u +
                SW128(r * 128 + cg * 16),
            Xh + (size_t)(rb + r) * 128 + kb * 64 + cg * 8);
    }
    CPCOMMIT();

    float acc[4][4][4];
#pragma unroll
    for (int i = 0; i < 4; i++)
#pragma unroll
        for (int j = 0; j < 4; j++)
#pragma unroll
            for (int e = 0; e < 4; e++) acc[i][j][e] = 0.0f;

    const uint32_t swz = (uint32_t)(lane & 7) << 4;
    uint32_t arow[4], brow[4];
#pragma unroll
    for (int t = 0; t < 4; t++) {
        arow[t] = (uint32_t)((wm * 64 + t * 16 + (lane & 15)) * 128);
        brow[t] = (uint32_t)((wn * 32 + t * 8 + (lane & 7)) * 128);
    }
    const uint32_t akh = (uint32_t)((lane >> 4) * 16);
    const uint32_t bkh = (uint32_t)(((lane >> 3) & 1) * 16);

    CPWAIT(0);
    __syncthreads();

#pragma unroll
    for (int ks = 0; ks < 8; ks++) {
        uint32_t kbo = (uint32_t)(ks >> 2) * 16384u;
        uint32_t axk = ((uint32_t)((ks & 3) * 32) + akh) ^ swz;
        uint32_t bxk = ((uint32_t)((ks & 3) * 32) + bkh) ^ swz;
        uint32_t ah[4][4], bh[4][2];
#pragma unroll
        for (int t = 0; t < 4; t++) {
            ldmx4(ah[t], sb + kbo + arow[t] + axk);
            ldmx2(bh[t], sb + 32768u + kbo + brow[t] + bxk);
        }
#pragma unroll
        for (int tm = 0; tm < 4; tm++)
#pragma unroll
            for (int tn = 0; tn < 4; tn++)
                mma16816(acc[tm][tn], ah[tm], bh[tn]);
    }

    const int gi0 = ooff + bi * 128;
    const int gj0 = ooff + bj * 128;
    float* sf = (float*)(smem + 65536);   // [128][69]

    const int r = tid >> 1;                // direct-output row 0..127
    const int ch = (tid & 1) * 32;         // 32-col chunk within the 64-col half
    const int mc = tid >> 2;               // mirror column 0..63
    const int mchunk = tid & 3;            // mirror 32-row chunk

    float sdeg = 0.0f;

#pragma unroll
    for (int h = 0; h < 2; h++) {
        __syncthreads();
        // stage sigmoid(acc) for columns [h*64, h*64+64)
        if ((wn >> 1) == h) {
#pragma unroll
            for (int tm = 0; tm < 4; tm++)
#pragma unroll
                for (int tn = 0; tn < 4; tn++) {
                    int r0 = wm * 64 + tm * 16 + (lane >> 2);
                    int cs = (wn & 1) * 32 + tn * 8 + 2 * (lane & 3);
                    sf[r0 * 69 + cs]           = sigm(acc[tm][tn][0]);
                    sf[r0 * 69 + cs + 1]       = sigm(acc[tm][tn][1]);
                    sf[(r0 + 8) * 69 + cs]     = sigm(acc[tm][tn][2]);
                    sf[(r0 + 8) * 69 + cs + 1] = sigm(acc[tm][tn][3]);
                }
        }
        __syncthreads();

        if (mode == 0) {
            // direct rows
            float v[32];
#pragma unroll
            for (int c = 0; c < 32; c++) {
                v[c] = sf[r * 69 + ch + c];
                sdeg += v[c];
            }
            bf16* drow = Ph + (size_t)(gi0 + r) * MM + gj0 + h * 64 + ch;
#pragma unroll
            for (int q = 0; q < 4; q++) {
                uint4 o;
                o.x = pkh(v[q*8+0], v[q*8+1]); o.y = pkh(v[q*8+2], v[q*8+3]);
                o.z = pkh(v[q*8+4], v[q*8+5]); o.w = pkh(v[q*8+6], v[q*8+7]);
                *(uint4*)(drow + q * 8) = o;
            }
            // mirror (transposed) rows + mirror deg
            if (bi != bj) {
                float w[32];
                float ms = 0.0f;
#pragma unroll
                for (int c = 0; c < 32; c++) {
                    w[c] = sf[(mchunk * 32 + c) * 69 + mc];
                    ms += w[c];
                }
                bf16* mrow = Ph + (size_t)(gj0 + h * 64 + mc) * MM + gi0 + mchunk * 32;
#pragma unroll
                for (int q = 0; q < 4; q++) {
                    uint4 o;
                    o.x = pkh(w[q*8+0], w[q*8+1]); o.y = pkh(w[q*8+2], w[q*8+3]);
                    o.z = pkh(w[q*8+4], w[q*8+5]); o.w = pkh(w[q*8+6], w[q*8+7]);
                    *(uint4*)(mrow + q * 8) = o;
                }
                ms += __shfl_xor_sync(0xffffffffu, ms, 1);
                ms += __shfl_xor_sync(0xffffffffu, ms, 2);
                if (mchunk == 0 && degp)
                    degp[(size_t)bi * MM + gj0 + h * 64 + mc] = ms;
            }
        } else {
            float* drow = Pf + (size_t)(gi0 + r) * MM + gj0 + h * 64 + ch;
#pragma unroll
            for (int q = 0; q < 8; q++) {
                float4 o = make_float4(sf[r * 69 + ch + q*4], sf[r * 69 + ch + q*4+1],
                                       sf[r * 69 + ch + q*4+2], sf[r * 69 + ch + q*4+3]);
                *(float4*)(drow + q * 4) = o;
            }
            if (bi != bj) {
                float* mrow = Pf + (size_t)(gj0 + h * 64 + mc) * MM + gi0 + mchunk * 32;
#pragma unroll
                for (int q = 0; q < 8; q++) {
                    float4 o = make_float4(sf[(mchunk*32 + q*4+0) * 69 + mc],
                                           sf[(mchunk*32 + q*4+1) * 69 + mc],
                                           sf[(mchunk*32 + q*4+2) * 69 + mc],
                                           sf[(mchunk*32 + q*4+3) * 69 + mc]);
                    *(float4*)(mrow + q * 4) = o;
                }
            }
        }
    }

    if (mode == 0 && degp) {
        float full = sdeg + __shfl_xor_sync(0xffffffffu, sdeg, 1);
        if (!(tid & 1)) degp[(size_t)bj * MM + gi0 + r] = full;
    }
}

// ------------------------ small elementwise kernels ------------------------
// fp32 -> bf16 convert (row-major), n4 float4 groups
__global__ __launch_bounds__(256) void cvt_h(const float* __restrict__ s,
                                             bf16* __restrict__ dh, int n4)
{
    int i = blockIdx.x * 256 + threadIdx.x;
    if (i >= n4) return;
    float4 v = ((const float4*)s)[i];
    uint2 h;
    h.x = pkh(v.x, v.y);
    h.y = pkh(v.z, v.w);
    ((uint2*)dh)[i] = h;
}

// transpose-convert: src [R x C] fp32 -> dst [C x R] bf16
__global__ void tcvt_h(const float* __restrict__ src, bf16* __restrict__ dh,
                       int R, int C)
{
    __shared__ float t[32][33];
    int c0 = blockIdx.x * 32, r0 = blockIdx.y * 32;
    for (int i = threadIdx.y; i < 32; i += 8)
        t[i][threadIdx.x] = src[(size_t)(r0 + i) * C + c0 + threadIdx.x];
    __syncthreads();
    for (int i = threadIdx.y; i < 32; i += 8)
        dh[(size_t)(c0 + i) * R + r0 + threadIdx.x] = __float2bfloat16(t[threadIdx.x][i]);
}

// Yt[c][j] = dinv[j] * part[j][c]  (bf16)
__global__ void ytrans(const float* __restrict__ part, const float* __restrict__ dinv,
                       bf16* __restrict__ yh)
{
    __shared__ float t[32][33];
    int j0 = blockIdx.x * 32, c0 = blockIdx.y * 32;
    for (int i = threadIdx.y; i < 32; i += 8)
        t[i][threadIdx.x] = part[(size_t)(j0 + i) * 128 + c0 + threadIdx.x] * dinv[j0 + i];
    __syncthreads();
    for (int i = threadIdx.y; i < 32; i += 8)
        yh[(size_t)(c0 + i) * MM + j0 + threadIdx.x] = __float2bfloat16(t[threadIdx.x][i]);
}

// Xu = relu(dinv[i]*(sum of 4 partials) + bias[c]) -> bf16
__global__ __launch_bounds__(256) void xcombine4(const float* __restrict__ part,
    const float* __restrict__ dinv, const float* __restrict__ bias,
    bf16* __restrict__ xh)
{
    int idx = blockIdx.x * 256 + threadIdx.x;
    int base = idx * 4, row = base >> 7, c = base & 127;
    float4 a = ((const float4*)part)[idx];
    float4 b = ((const float4*)(part + (size_t)MM * DD))[idx];
    float4 d = ((const float4*)(part + (size_t)2 * MM * DD))[idx];
    float4 e = ((const float4*)(part + (size_t)3 * MM * DD))[idx];
    float di = dinv[row];
    float v0 = fmaxf(di * (a.x + b.x + d.x + e.x) + bias[c + 0], 0.0f);
    float v1 = fmaxf(di * (a.y + b.y + d.y + e.y) + bias[c + 1], 0.0f);
    float v2 = fmaxf(di * (a.z + b.z + d.z + e.z) + bias[c + 2], 0.0f);
    float v3 = fmaxf(di * (a.w + b.w + d.w + e.w) + bias[c + 3], 0.0f);
    uint2 h;
    h.x = pkh(v0, v1);
    h.y = pkh(v2, v3);
    ((uint2*)xh)[idx] = h;
}

// new_nodes rows: Xu[4096+r] = p0+p1 + bup[r]
__global__ __launch_bounds__(256) void up_combine(const float* __restrict__ part,
    const float* __restrict__ bup, bf16* __restrict__ xh)
{
    int idx = blockIdx.x * 256 + threadIdx.x;
    int base = idx * 4, row = base >> 7;
    float4 a = ((const float4*)part)[idx];
    float4 b = ((const float4*)(part + (size_t)MM * DD))[idx];
    float bu = bup[row];
    uint2 h;
    h.x = pkh(a.x + b.x + bu, a.y + b.y + bu);
    h.y = pkh(a.z + b.z + bu, a.w + b.w + bu);
    ((uint2*)(xh + (size_t)NN * DD))[idx] = h;
}

// A (fp32) -> bf16 into 3 quadrants of Phi
__global__ __launch_bounds__(256) void buildA(const float* __restrict__ A,
                                              bf16* __restrict__ Ph)
{
    int idx = blockIdx.x * 256 + threadIdx.x;
    int i = idx >> 10, j4 = idx & 1023;
    float4 v = ((const float4*)A)[(size_t)i * 1024 + j4];
    uint2 h;
    h.x = pkh(v.x, v.y);
    h.y = pkh(v.z, v.w);
    size_t o0 = (size_t)i * MM + j4 * 4;
    *(uint2*)(Ph + o0) = h;
    *(uint2*)(Ph + o0 + NN) = h;
    *(uint2*)(Ph + (size_t)(i + NN) * MM + j4 * 4) = h;
}

// fp32 row sums of A (deterministic tree reduce)
__global__ __launch_bounds__(256) void rsA_kernel(const float* __restrict__ A,
                                                  float* __restrict__ rsA)
{
    __shared__ float red[256];
    const float4* p = (const float4*)(A + (size_t)blockIdx.x * NN);
    float s = 0.0f;
    for (int j = threadIdx.x; j < NN / 4; j += 256) {
        float4 v = p[j];
        s += (v.x + v.y) + (v.z + v.w);
    }
    red[threadIdx.x] = s;
    __syncthreads();
    for (int st = 128; st > 0; st >>= 1) {
        if (threadIdx.x < st) red[threadIdx.x] += red[threadIdx.x + st];
        __syncthreads();
    }
    if (threadIdx.x == 0) rsA[blockIdx.x] = red[0];
}

// init deg: rows<N: 2*rowsum(A); rows>=N: rowsum(A) + sum of 32 S-partials
__global__ __launch_bounds__(256) void deg_init(const float* __restrict__ rsA,
    const float* __restrict__ degp, float* __restrict__ dinv)
{
    int i = blockIdx.x * 256 + threadIdx.x;
    float d;
    if (i < NN) {
        d = 2.0f * rsA[i];
    } else {
        d = rsA[i - NN];
#pragma unroll
        for (int s = 0; s < 32; s++) d += degp[(size_t)s * MM + i];
    }
    dinv[i] = d > 0.0f ? rsqrtf(d) : 0.0f;
}

__global__ __launch_bounds__(256) void deg_reduce(const float* __restrict__ degp,
                                                  float* __restrict__ dinv)
{
    int i = blockIdx.x * 256 + threadIdx.x;
    float d = 0.0f;
#pragma unroll
    for (int s = 0; s < 64; s++) d += degp[(size_t)s * MM + i];
    dinv[i] = d > 0.0f ? rsqrtf(d) : 0.0f;
}

// ---------------------------------------------------------------------------
extern "C" void kernel_launch(void* const* d_in, const int* in_sizes, int n_in,
                              void* d_out, int out_size)
{
    const float* X   = (const float*)d_in[0];
    const float* A   = (const float*)d_in[1];
    const float* Wup = (const float*)d_in[2];
    const float* bup = (const float*)d_in[3];
    const float* W1  = (const float*)d_in[4];
    const float* b1  = (const float*)d_in[5];
    const float* W2  = (const float*)d_in[6];
    const float* b2  = (const float*)d_in[7];
    float* P = (float*)d_out;

    bf16 *Phi, *Xuh, *Yth, *Xth, *W1h, *W2h, *Wuh;
    float *part, *degp, *dinv, *rsA;
    cudaGetSymbolAddress((void**)&Phi, g_Phi);
    cudaGetSymbolAddress((void**)&Xuh, g_Xuh);
    cudaGetSymbolAddress((void**)&Yth, g_Yth);
    cudaGetSymbolAddress((void**)&Xth, g_Xth);
    cudaGetSymbolAddress((void**)&W1h, g_W1h);
    cudaGetSymbolAddress((void**)&W2h, g_W2h);
    cudaGetSymbolAddress((void**)&Wuh, g_Wuh);
    cudaGetSymbolAddress((void**)&part, g_part);
    cudaGetSymbolAddress((void**)&degp, g_degp);
    cudaGetSymbolAddress((void**)&dinv, g_dinv);
    cudaGetSymbolAddress((void**)&rsA, g_rsA);

    cudaFuncSetAttribute(adj_single, cudaFuncAttributeMaxDynamicSharedMemorySize, SGL_SMEM);
    cudaFuncSetAttribute(xxt_single, cudaFuncAttributeMaxDynamicSharedMemorySize, XXT_SMEM);

    // ---- init conversions ----
    cvt_h<<<(NN * DD / 4 + 255) / 256, 256>>>(X, Xuh, NN * DD / 4);
    tcvt_h<<<dim3(DD / 32, NN / 32), dim3(32, 8)>>>(X, Xth, NN, DD);
    cvt_h<<<(NN * NN / 4 + 255) / 256, 256>>>(Wup, Wuh, NN * NN / 4);
    tcvt_h<<<dim3(4, 4), dim3(32, 8)>>>(W1, W1h, DD, DD);
    tcvt_h<<<dim3(4, 4), dim3(32, 8)>>>(W2, W2h, DD, DD);

    // new_nodes = Wup @ X (+ bup)
    adj_single<<<dim3(NN / 128, 2), 256, SGL_SMEM>>>(Wuh, NN, Xth, NN,
                                                     part, NN / 2, MM * DD);
    up_combine<<<NN * DD / 4 / 256, 256>>>(part, bup, Xuh);

    // initial block adjacency (bf16) + fused S row-sum partials
    buildA<<<NN * NN / 4 / 256, 256>>>(A, Phi);
    rsA_kernel<<<NN, 256>>>(A, rsA);
    xxt_single<<<32 * 33 / 2, 256, XXT_SMEM>>>(Xuh + (size_t)NN * DD, NN,
                                               Phi, nullptr, degp, 0);
    deg_init<<<MM / 256, 256>>>(rsA, degp, dinv);

    for (int it = 0; it < 3; it++) {
        // conv1 (dinv from previous rebuild / init)
        adj_single<<<dim3(MM / 128, 1), 256, SGL_SMEM>>>(Xuh, DD, W1h, DD,
                                                         part, DD, MM * DD);
        ytrans<<<dim3(MM / 32, DD / 32), dim3(32, 8)>>>(part, dinv, Yth);
        adj_single<<<dim3(MM / 128, 4), 256, SGL_SMEM>>>(Phi, MM, Yth, MM,
                                                         part, MM / 4, MM * DD);
        xcombine4<<<MM * DD / 4 / 256, 256>>>(part, dinv, b1, Xuh);
        // mid-loop adjacency rebuild + fused deg partials
        xxt_single<<<64 * 65 / 2, 256, XXT_SMEM>>>(Xuh, 0, Phi, nullptr, degp, 0);
        deg_reduce<<<MM / 256, 256>>>(degp, dinv);
        // conv2
        adj_single<<<dim3(MM / 128, 1), 256, SGL_SMEM>>>(Xuh, DD, W2h, DD,
                                                         part, DD, MM * DD);
        ytrans<<<dim3(MM / 32, DD / 32), dim3(32, 8)>>>(part, dinv, Yth);
        adj_single<<<dim3(MM / 128, 4), 256, SGL_SMEM>>>(Phi, MM, Yth, MM,
                                                         part, MM / 4, MM * DD);
        xcombine4<<<MM * DD / 4 / 256, 256>>>(part, dinv, b2, Xuh);
    }

    // final A_out = sigmoid(Xu Xu^T) -> d_out (fp32)
    xxt_single<<<64 * 65 / 2, 256, XXT_SMEM>>>(Xuh, 0, nullptr, P, nullptr, 1);

    (void)in_sizes; (void)n_in; (void)out_size;
}